// round 1
// baseline (speedup 1.0000x reference)
#include <cuda_runtime.h>

// ---------------- problem constants ----------------
#define MAX_E 120000
#define MAX_N 5000

// ---------------- scratch (static __device__, allocation-free) ----------------
__device__ float g_cut[MAX_E];
__device__ float g_lat[MAX_E * 128];
__device__ float g_w0[MAX_E * 64];      // env0 output (w_edge | w_env)
__device__ float g_wenv1[MAX_E * 32];   // env1 output; reused for fw (E x 16) at the end
__device__ float g_fs[MAX_E * 16];
__device__ float g_fv[MAX_E * 48];
__device__ float g_scal[MAX_E * 32];    // interleaved s1,s2 (latent_in[:,128:160])
__device__ float g_V[MAX_E * 144];      // V[e, p(3), u(16), i(3)]
__device__ float g_env_s[MAX_N * 16];
__device__ float g_env_v[MAX_N * 48];
__device__ float g_env_s2[MAX_N * 16];
__device__ float g_env_v2[MAX_N * 48];

// ---------------- math constants ----------------
__device__ __constant__ float kDummy = 0.f;
constexpr float C_OLD    = 0.8944271909999159f;   // 1/sqrt(1.25)
constexpr float A_C_OLD  = 0.4472135954999579f;   // 0.5/sqrt(1.25)
constexpr float INV_S3   = 0.5773502691896258f;   // 1/sqrt(3)
constexpr float INV_S2   = 0.7071067811865476f;   // 1/sqrt(2)
constexpr float C_FS     = 0.17677669529663687f;  // 1/sqrt(2*MUL)
constexpr float C_FV     = 0.14433756729740643f;  // 1/sqrt(3*MUL)
constexpr float NORM_LIN = 0.05590169943749474f;  // (1/sqrt(20)) * (1/sqrt(16))
constexpr float INV_SM   = 0.25f;                 // 1/sqrt(16)

__device__ __forceinline__ float silu_f(float x) { return x / (1.f + __expf(-x)); }

// ---------------- shared GEMM building blocks ----------------
// Tile: 64 edges per block, 256 threads.
// GEMM1 (X[64,IN] @ W1[IN,128] -> silu -> Hs[64,128]): micro-tile 4 edges x 8 hid.
template <int IN>
__device__ __forceinline__ void gemm1_silu(const float* Xs, const float* __restrict__ W1,
                                           float* Hs, int t) {
    const int eg = t >> 4;   // 16 groups of 4 edges
    const int hg = t & 15;   // 16 groups of 8 hidden
    float acc[4][8];
#pragma unroll
    for (int i = 0; i < 4; i++)
#pragma unroll
        for (int j = 0; j < 8; j++) acc[i][j] = 0.f;
#pragma unroll 4
    for (int k = 0; k < IN; k++) {
        const float4 wa = *reinterpret_cast<const float4*>(W1 + k * 128 + hg * 8);
        const float4 wb = *reinterpret_cast<const float4*>(W1 + k * 128 + hg * 8 + 4);
#pragma unroll
        for (int i = 0; i < 4; i++) {
            const float x = Xs[(eg * 4 + i) * IN + k];
            acc[i][0] = fmaf(x, wa.x, acc[i][0]);
            acc[i][1] = fmaf(x, wa.y, acc[i][1]);
            acc[i][2] = fmaf(x, wa.z, acc[i][2]);
            acc[i][3] = fmaf(x, wa.w, acc[i][3]);
            acc[i][4] = fmaf(x, wb.x, acc[i][4]);
            acc[i][5] = fmaf(x, wb.y, acc[i][5]);
            acc[i][6] = fmaf(x, wb.z, acc[i][6]);
            acc[i][7] = fmaf(x, wb.w, acc[i][7]);
        }
    }
#pragma unroll
    for (int i = 0; i < 4; i++)
#pragma unroll
        for (int j = 0; j < 8; j++)
            Hs[(eg * 4 + i) * 128 + hg * 8 + j] = silu_f(acc[i][j]);
}

// Load 64 x IN tile into smem; X = [Xa (width WA) | Xb (width IN-WA)], zero-pad tail edges.
template <int IN, int WA>
__device__ __forceinline__ void load_xs(float* Xs, const float* __restrict__ Xa,
                                        const float* __restrict__ Xb, int e0, int E, int t) {
    for (int idx = t; idx < 64 * IN; idx += 256) {
        const int le = idx / IN;
        const int c = idx - le * IN;
        const int e = e0 + le;
        float v = 0.f;
        if (e < E) {
            if (c < WA) v = Xa[e * WA + c];
            else        v = Xb[e * (IN - WA) + (c - WA)];
        }
        Xs[idx] = v;
    }
}

// ---------------- generic 2-layer MLP kernel: Y = silu(X@W1)@W2 ----------------
// EPI 0: plain store.  EPI 1: lat blend  g_lat = C_OLD*g_lat + A_C_OLD*cut*val
template <int IN, int WA, int OUT, int EPI>
__global__ void __launch_bounds__(256)
k_mlp(const float* __restrict__ Xa, const float* __restrict__ Xb,
      const float* __restrict__ W1, const float* __restrict__ W2,
      float* __restrict__ Y, int E) {
    extern __shared__ float sm[];
    float* Xs = sm;
    float* Hs = sm + 64 * IN;
    const int t = threadIdx.x;
    const int e0 = blockIdx.x * 64;

    load_xs<IN, WA>(Xs, Xa, Xb, e0, E, t);
    __syncthreads();
    gemm1_silu<IN>(Xs, W1, Hs, t);
    __syncthreads();

    constexpr int OPT = (OUT >= 32) ? 8 : 4;
    constexpr int NOG = OUT / OPT;           // 128->16, 64->8, 32->4, 16->4
    constexpr int EPT = (NOG >= 4) ? NOG / 4 : 1;
    const int og = t % NOG;
    const int eg = t / NOG;

    float acc[EPT][OPT];
#pragma unroll
    for (int i = 0; i < EPT; i++)
#pragma unroll
        for (int j = 0; j < OPT; j++) acc[i][j] = 0.f;

#pragma unroll 4
    for (int k = 0; k < 128; k++) {
        const float* wr = W2 + k * OUT + og * OPT;
        float w[OPT];
        {
            float4 t0 = *reinterpret_cast<const float4*>(wr);
            w[0] = t0.x; w[1] = t0.y; w[2] = t0.z; w[3] = t0.w;
            if (OPT == 8) {
                float4 t1 = *reinterpret_cast<const float4*>(wr + 4);
                w[4] = t1.x; w[5] = t1.y; w[6] = t1.z; w[7] = t1.w;
            }
        }
#pragma unroll
        for (int i = 0; i < EPT; i++) {
            const float h = Hs[(eg * EPT + i) * 128 + k];
#pragma unroll
            for (int j = 0; j < OPT; j++) acc[i][j] = fmaf(h, w[j], acc[i][j]);
        }
    }

#pragma unroll
    for (int i = 0; i < EPT; i++) {
        const int e = e0 + eg * EPT + i;
        if (e >= E) continue;
        if (EPI == 0) {
#pragma unroll
            for (int j = 0; j < OPT; j++) Y[e * OUT + og * OPT + j] = acc[i][j];
        } else {
            const float ac = A_C_OLD * g_cut[e];
#pragma unroll
            for (int j = 0; j < OPT; j++) {
                const int o = og * OPT + j;
                g_lat[e * 128 + o] = C_OLD * g_lat[e * 128 + o] + ac * acc[i][j];
            }
        }
    }
}

// ---------------- first stage: gather x2b + MLP(16->128->128) * cut ----------------
__global__ void __launch_bounds__(256)
k_first(const float* __restrict__ node_attrs, const float* __restrict__ edge_embed,
        const float* __restrict__ edge_u, const int* __restrict__ edge_index,
        const float* __restrict__ W1, const float* __restrict__ W2, int E) {
    extern __shared__ float sm[];
    float* Xs = sm;             // 64 x 16
    float* Hs = sm + 64 * 16;   // 64 x 128
    const int t = threadIdx.x;
    const int e0 = blockIdx.x * 64;

    for (int idx = t; idx < 64 * 16; idx += 256) {
        const int le = idx >> 4, c = idx & 15;
        const int e = e0 + le;
        float v = 0.f;
        if (e < E) {
            if (c < 4)       v = node_attrs[edge_index[e] * 4 + c];
            else if (c < 8)  v = node_attrs[edge_index[E + e] * 4 + (c - 4)];
            else             v = edge_embed[e * 8 + (c - 8)];
        }
        Xs[idx] = v;
    }
    if (t < 64) {
        const int e = e0 + t;
        if (e < E) {
            const float u = edge_u[e];
            const float u2 = u * u, u3 = u2 * u, u6 = u3 * u3;
            const float f = 1.f - 28.f * u6 + 48.f * u6 * u - 21.f * u6 * u2;
            g_cut[e] = (u < 1.f) ? f : 0.f;
        }
    }
    __syncthreads();
    gemm1_silu<16>(Xs, W1, Hs, t);
    __syncthreads();

    const int eg = t >> 4, og = t & 15;
    float acc[4][8];
#pragma unroll
    for (int i = 0; i < 4; i++)
#pragma unroll
        for (int j = 0; j < 8; j++) acc[i][j] = 0.f;
#pragma unroll 4
    for (int k = 0; k < 128; k++) {
        const float4 wa = *reinterpret_cast<const float4*>(W2 + k * 128 + og * 8);
        const float4 wb = *reinterpret_cast<const float4*>(W2 + k * 128 + og * 8 + 4);
#pragma unroll
        for (int i = 0; i < 4; i++) {
            const float h = Hs[(eg * 4 + i) * 128 + k];
            acc[i][0] = fmaf(h, wa.x, acc[i][0]);
            acc[i][1] = fmaf(h, wa.y, acc[i][1]);
            acc[i][2] = fmaf(h, wa.z, acc[i][2]);
            acc[i][3] = fmaf(h, wa.w, acc[i][3]);
            acc[i][4] = fmaf(h, wb.x, acc[i][4]);
            acc[i][5] = fmaf(h, wb.y, acc[i][5]);
            acc[i][6] = fmaf(h, wb.z, acc[i][6]);
            acc[i][7] = fmaf(h, wb.w, acc[i][7]);
        }
    }
#pragma unroll
    for (int i = 0; i < 4; i++) {
        const int e = e0 + eg * 4 + i;
        if (e >= E) continue;
        const float cc = g_cut[e];
#pragma unroll
        for (int j = 0; j < 8; j++) g_lat[e * 128 + og * 8 + j] = cc * acc[i][j];
    }
}

// ---------------- weighter for fs/fv (from w0[:, :32]) ----------------
__global__ void k_weighter(const float* __restrict__ edge_attr, int E) {
    const int idx = blockIdx.x * blockDim.x + threadIdx.x;
    if (idx >= E * 16) return;
    const int e = idx >> 4, u = idx & 15;
    const float ws = g_w0[e * 64 + 2 * u];
    const float wv = g_w0[e * 64 + 2 * u + 1];
    const float a1 = edge_attr[e * 4 + 1], a2 = edge_attr[e * 4 + 2], a3 = edge_attr[e * 4 + 3];
    g_fs[e * 16 + u] = ws * edge_attr[e * 4 + 0];
    g_fv[e * 48 + u * 3 + 0] = wv * a1;
    g_fv[e * 48 + u * 3 + 1] = wv * a2;
    g_fv[e * 48 + u * 3 + 2] = wv * a3;
}

// ---------------- segment-sum scatter of env weights ----------------
__global__ void k_scatter(const float* __restrict__ wenv, int stride, int off,
                          const float* __restrict__ edge_attr,
                          const int* __restrict__ edge_index, int E) {
    const int idx = blockIdx.x * blockDim.x + threadIdx.x;
    if (idx >= E * 16) return;
    const int e = idx >> 4, u = idx & 15;
    const int c = edge_index[e];  // center
    const float ws = wenv[e * stride + off + 2 * u];
    const float wv = wenv[e * stride + off + 2 * u + 1];
    atomicAdd(&g_env_s[c * 16 + u], ws * edge_attr[e * 4 + 0]);
    atomicAdd(&g_env_v[c * 48 + u * 3 + 0], wv * edge_attr[e * 4 + 1]);
    atomicAdd(&g_env_v[c * 48 + u * 3 + 1], wv * edge_attr[e * 4 + 2]);
    atomicAdd(&g_env_v[c * 48 + u * 3 + 2], wv * edge_attr[e * 4 + 3]);
}

// ---------------- per-node 16x16 env linears (norm * inv_sm folded in) ----------------
__global__ void k_envlin(const float* __restrict__ Ws, const float* __restrict__ Wv, int N) {
    const int idx = blockIdx.x * blockDim.x + threadIdx.x;
    if (idx >= N * 16) return;
    const int n = idx >> 4, v = idx & 15;
    float s = 0.f, v0 = 0.f, v1 = 0.f, v2 = 0.f;
#pragma unroll
    for (int u = 0; u < 16; u++) {
        const float wsv = Ws[u * 16 + v];
        const float wvv = Wv[u * 16 + v];
        s  = fmaf(g_env_s[n * 16 + u], wsv, s);
        v0 = fmaf(g_env_v[n * 48 + u * 3 + 0], wvv, v0);
        v1 = fmaf(g_env_v[n * 48 + u * 3 + 1], wvv, v1);
        v2 = fmaf(g_env_v[n * 48 + u * 3 + 2], wvv, v2);
    }
    g_env_s2[n * 16 + v] = s * NORM_LIN;
    g_env_v2[n * 48 + v * 3 + 0] = v0 * NORM_LIN;
    g_env_v2[n * 48 + v * 3 + 1] = v1 * NORM_LIN;
    g_env_v2[n * 48 + v * 3 + 2] = v2 * NORM_LIN;
}

// ---------------- per-edge combine: s1,s2 and V = [v1,v2,v3] ----------------
__global__ void k_combine(const int* __restrict__ edge_index, int E) {
    const int idx = blockIdx.x * blockDim.x + threadIdx.x;
    if (idx >= E * 16) return;
    const int e = idx >> 4, u = idx & 15;
    const int c = edge_index[e];
    const float es  = g_env_s2[c * 16 + u];
    const float ev0 = g_env_v2[c * 48 + u * 3 + 0];
    const float ev1 = g_env_v2[c * 48 + u * 3 + 1];
    const float ev2 = g_env_v2[c * 48 + u * 3 + 2];
    const float fsv = g_fs[e * 16 + u];
    const float fv0 = g_fv[e * 48 + u * 3 + 0];
    const float fv1 = g_fv[e * 48 + u * 3 + 1];
    const float fv2 = g_fv[e * 48 + u * 3 + 2];

    g_scal[e * 32 + 2 * u]     = fsv * es;
    g_scal[e * 32 + 2 * u + 1] = (fv0 * ev0 + fv1 * ev1 + fv2 * ev2) * INV_S3;

    float* Vp = &g_V[e * 144];
    Vp[u * 3 + 0] = fsv * ev0;          // v1
    Vp[u * 3 + 1] = fsv * ev1;
    Vp[u * 3 + 2] = fsv * ev2;
    Vp[48 + u * 3 + 0] = fv0 * es;      // v2
    Vp[48 + u * 3 + 1] = fv1 * es;
    Vp[48 + u * 3 + 2] = fv2 * es;
    Vp[96 + u * 3 + 0] = (fv1 * ev2 - fv2 * ev1) * INV_S2;  // v3 = fv x ev
    Vp[96 + u * 3 + 1] = (fv2 * ev0 - fv0 * ev2) * INV_S2;
    Vp[96 + u * 3 + 2] = (fv0 * ev1 - fv1 * ev0) * INV_S2;
}

// ---------------- fused l2w MLP (160->128->1280) + bilinear contraction ----------------
// Never materializes lw in HBM: Hs @ W2 is computed 128 columns at a time into smem,
// immediately contracted with S (in Xs scal region) / V (global, L1-cached).
__global__ void __launch_bounds__(256)
k_l2w(const float* __restrict__ W1, const float* __restrict__ W2, int E) {
    extern __shared__ float sm[];
    float* Xs = sm;                  // 64 x 160
    float* Hs = Xs + 64 * 160;       // 64 x 128
    float* Ls = Hs + 64 * 128;       // 64 x 128 (lw column chunk)
    const int t = threadIdx.x;
    const int e0 = blockIdx.x * 64;

    load_xs<160, 128>(Xs, g_lat, g_scal, e0, E, t);
    __syncthreads();
    gemm1_silu<160>(Xs, W1, Hs, t);
    __syncthreads();

    const int eg = t >> 4;   // 4 edges per thread (both phases)
    const int vv = t & 15;   // contraction output column v

    float facc[4] = {0.f, 0.f, 0.f, 0.f};
    float vacc[4][3] = {};

#pragma unroll 1
    for (int ch = 0; ch < 10; ch++) {
        // GEMM: Ls[64,128] = Hs @ W2[:, ch*128 : ch*128+128]
        float acc[4][8];
#pragma unroll
        for (int i = 0; i < 4; i++)
#pragma unroll
            for (int j = 0; j < 8; j++) acc[i][j] = 0.f;
#pragma unroll 4
        for (int k = 0; k < 128; k++) {
            const float* wr = W2 + k * 1280 + ch * 128 + vv * 8;
            const float4 wa = *reinterpret_cast<const float4*>(wr);
            const float4 wb = *reinterpret_cast<const float4*>(wr + 4);
#pragma unroll
            for (int i = 0; i < 4; i++) {
                const float h = Hs[(eg * 4 + i) * 128 + k];
                acc[i][0] = fmaf(h, wa.x, acc[i][0]);
                acc[i][1] = fmaf(h, wa.y, acc[i][1]);
                acc[i][2] = fmaf(h, wa.z, acc[i][2]);
                acc[i][3] = fmaf(h, wa.w, acc[i][3]);
                acc[i][4] = fmaf(h, wb.x, acc[i][4]);
                acc[i][5] = fmaf(h, wb.y, acc[i][5]);
                acc[i][6] = fmaf(h, wb.z, acc[i][6]);
                acc[i][7] = fmaf(h, wb.w, acc[i][7]);
            }
        }
        __syncthreads();  // previous chunk's contraction done reading Ls
#pragma unroll
        for (int i = 0; i < 4; i++)
#pragma unroll
            for (int j = 0; j < 8; j++)
                Ls[(eg * 4 + i) * 128 + vv * 8 + j] = acc[i][j];
        __syncthreads();  // Ls ready

        // contraction: 8 (p,u) rows in this chunk; lw[e, pu*16+v]
#pragma unroll
        for (int r = 0; r < 8; r++) {
            const int pu = ch * 8 + r;
#pragma unroll
            for (int i = 0; i < 4; i++) {
                const int el = eg * 4 + i;
                const float val = Ls[el * 128 + r * 16 + vv];
                if (pu < 32) {  // ws block: S[e,p,u] lives in Xs scal region
                    const int p = pu >> 4, u = pu & 15;
                    facc[i] = fmaf(Xs[el * 160 + 128 + 2 * u + p], val, facc[i]);
                } else {        // wv block: V from global (L1 broadcast across v threads)
                    const int q = pu - 32;
                    const int p = q >> 4, u = q & 15;
                    const int e = e0 + el;
                    if (e < E) {
                        const float* vp = &g_V[e * 144 + p * 48 + u * 3];
                        vacc[i][0] = fmaf(vp[0], val, vacc[i][0]);
                        vacc[i][1] = fmaf(vp[1], val, vacc[i][1]);
                        vacc[i][2] = fmaf(vp[2], val, vacc[i][2]);
                    }
                }
            }
        }
    }

#pragma unroll
    for (int i = 0; i < 4; i++) {
        const int e = e0 + eg * 4 + i;
        if (e >= E) continue;
        g_fs[e * 16 + vv] = C_FS * facc[i];
        g_fv[e * 48 + vv * 3 + 0] = C_FV * vacc[i][0];
        g_fv[e * 48 + vv * 3 + 1] = C_FV * vacc[i][1];
        g_fv[e * 48 + vv * 3 + 2] = C_FV * vacc[i][2];
    }
}

// ---------------- final output: out[e,i] = inv_sm * sum_u fw[e,u] * fv[e,u,i] ----------------
__global__ void k_out(float* __restrict__ out, int E) {
    const int idx = blockIdx.x * blockDim.x + threadIdx.x;
    if (idx >= E * 3) return;
    const int e = idx / 3, i = idx - e * 3;
    float acc = 0.f;
#pragma unroll
    for (int u = 0; u < 16; u++)
        acc = fmaf(g_wenv1[e * 16 + u], g_fv[e * 48 + u * 3 + i], acc);
    out[idx] = INV_SM * acc;
}

// ---------------- host driver ----------------
extern "C" void kernel_launch(void* const* d_in, const int* in_sizes, int n_in,
                              void* d_out, int out_size) {
    const float* edge_attr  = (const float*)d_in[0];
    const float* node_attrs = (const float*)d_in[1];
    const float* edge_embed = (const float*)d_in[2];
    const float* edge_u     = (const float*)d_in[3];
    const int*   edge_index = (const int*)d_in[4];
    const float* w2b1    = (const float*)d_in[5];
    const float* w2b2    = (const float*)d_in[6];
    const float* lat1_w1 = (const float*)d_in[7];
    const float* lat1_w2 = (const float*)d_in[8];
    const float* env0_w1 = (const float*)d_in[9];
    const float* env0_w2 = (const float*)d_in[10];
    const float* env1_w1 = (const float*)d_in[11];
    const float* env1_w2 = (const float*)d_in[12];
    const float* l2w0_w1 = (const float*)d_in[13];
    const float* l2w0_w2 = (const float*)d_in[14];
    const float* l2w1_w1 = (const float*)d_in[15];
    const float* l2w1_w2 = (const float*)d_in[16];
    const float* envlin_ws = (const float*)d_in[17];
    const float* envlin_wv = (const float*)d_in[18];
    const float* fl2w_w1 = (const float*)d_in[19];
    const float* fl2w_w2 = (const float*)d_in[20];
    float* out = (float*)d_out;

    const int E = in_sizes[0] / 4;
    const int N = in_sizes[1] / 4;
    if (E > MAX_E || N > MAX_N) return;

    float *p_lat, *p_scal, *p_w0, *p_wenv1, *p_env_s, *p_env_v;
    cudaGetSymbolAddress((void**)&p_lat, g_lat);
    cudaGetSymbolAddress((void**)&p_scal, g_scal);
    cudaGetSymbolAddress((void**)&p_w0, g_w0);
    cudaGetSymbolAddress((void**)&p_wenv1, g_wenv1);
    cudaGetSymbolAddress((void**)&p_env_s, g_env_s);
    cudaGetSymbolAddress((void**)&p_env_v, g_env_v);

    const size_t smA = (64 * 16 + 64 * 128) * sizeof(float);              // 36 KB
    const size_t smB = (64 * 128 + 64 * 128) * sizeof(float);             // 64 KB
    const size_t smC = (64 * 160 + 64 * 128) * sizeof(float);             // 72 KB
    const size_t smL = (64 * 160 + 64 * 128 + 64 * 128) * sizeof(float);  // 104 KB

    cudaFuncSetAttribute((const void*)k_first, cudaFuncAttributeMaxDynamicSharedMemorySize, (int)smA);
    cudaFuncSetAttribute((const void*)k_mlp<128,128,64,0>,  cudaFuncAttributeMaxDynamicSharedMemorySize, (int)smB);
    cudaFuncSetAttribute((const void*)k_mlp<128,128,32,0>,  cudaFuncAttributeMaxDynamicSharedMemorySize, (int)smB);
    cudaFuncSetAttribute((const void*)k_mlp<160,128,128,1>, cudaFuncAttributeMaxDynamicSharedMemorySize, (int)smC);
    cudaFuncSetAttribute((const void*)k_mlp<160,128,16,0>,  cudaFuncAttributeMaxDynamicSharedMemorySize, (int)smC);
    cudaFuncSetAttribute((const void*)k_l2w,                cudaFuncAttributeMaxDynamicSharedMemorySize, (int)smL);

    const int nb   = (E + 63) / 64;
    const int nb16 = (E * 16 + 255) / 256;

    // stage 0: x2b gather + MLP + cut
    k_first<<<nb, 256, smA>>>(node_attrs, edge_embed, edge_u, edge_index, w2b1, w2b2, E);
    // env0 MLP -> w0 (w_edge | w_env)
    k_mlp<128,128,64,0><<<nb, 256, smB>>>(p_lat, p_lat, env0_w1, env0_w2, p_w0, E);
    k_weighter<<<nb16, 256>>>(edge_attr, E);

    // ---- layer 0 ----
    cudaMemsetAsync(p_env_s, 0, (size_t)N * 16 * sizeof(float));
    cudaMemsetAsync(p_env_v, 0, (size_t)N * 48 * sizeof(float));
    k_scatter<<<nb16, 256>>>(p_w0, 64, 32, edge_attr, edge_index, E);
    k_envlin<<<(N * 16 + 255) / 256, 256>>>(envlin_ws, envlin_wv, N);
    k_combine<<<nb16, 256>>>(edge_index, E);
    k_l2w<<<nb, 256, smL>>>(l2w0_w1, l2w0_w2, E);

    // ---- layer 1 ----
    k_mlp<160,128,128,1><<<nb, 256, smC>>>(p_lat, p_scal, lat1_w1, lat1_w2, p_lat, E);  // lat blend
    k_mlp<128,128,32,0><<<nb, 256, smB>>>(p_lat, p_lat, env1_w1, env1_w2, p_wenv1, E);
    cudaMemsetAsync(p_env_s, 0, (size_t)N * 16 * sizeof(float));
    cudaMemsetAsync(p_env_v, 0, (size_t)N * 48 * sizeof(float));
    k_scatter<<<nb16, 256>>>(p_wenv1, 32, 0, edge_attr, edge_index, E);
    k_envlin<<<(N * 16 + 255) / 256, 256>>>(envlin_ws + 256, envlin_wv + 256, N);
    k_combine<<<nb16, 256>>>(edge_index, E);
    k_l2w<<<nb, 256, smL>>>(l2w1_w1, l2w1_w2, E);

    // ---- final: fw MLP + contraction with fv ----
    k_mlp<160,128,16,0><<<nb, 256, smC>>>(p_lat, p_scal, fl2w_w1, fl2w_w2, p_wenv1, E);
    k_out<<<(E * 3 + 255) / 256, 256>>>(out, E);
}

// round 2
// speedup vs baseline: 1.1483x; 1.1483x over previous
#include <cuda_runtime.h>

// ---------------- problem constants ----------------
#define MAX_E 120000
#define MAX_N 5000

typedef unsigned long long u64;

// ---------------- scratch (static __device__, allocation-free) ----------------
__device__ float g_cut[MAX_E];
__device__ float g_lat[MAX_E * 128];
__device__ float g_w0[MAX_E * 64];      // env0 output (w_edge | w_env)
__device__ float g_wenv1[MAX_E * 32];   // env1 output; reused for fw (E x 16) at the end
__device__ float g_fs[MAX_E * 16];
__device__ float g_fv[MAX_E * 48];
__device__ float g_scal[MAX_E * 32];    // interleaved s1,s2 (latent_in[:,128:160])
__device__ float g_V[MAX_E * 144];      // V[e, p(3), u(16), i(3)]
__device__ float g_env_s[MAX_N * 16];
__device__ float g_env_v[MAX_N * 48];
__device__ float g_env_s2[MAX_N * 16];
__device__ float g_env_v2[MAX_N * 48];

// ---------------- math constants ----------------
constexpr float C_OLD    = 0.8944271909999159f;   // 1/sqrt(1.25)
constexpr float A_C_OLD  = 0.4472135954999579f;   // 0.5/sqrt(1.25)
constexpr float INV_S3   = 0.5773502691896258f;   // 1/sqrt(3)
constexpr float INV_S2   = 0.7071067811865476f;   // 1/sqrt(2)
constexpr float C_FS     = 0.17677669529663687f;  // 1/sqrt(2*MUL)
constexpr float C_FV     = 0.14433756729740643f;  // 1/sqrt(3*MUL)
constexpr float NORM_LIN = 0.05590169943749474f;  // (1/sqrt(20)) * (1/sqrt(16))
constexpr float INV_SM   = 0.25f;                 // 1/sqrt(16)

__device__ __forceinline__ float silu_f(float x) { return x / (1.f + __expf(-x)); }

// ---------------- packed f32x2 helpers ----------------
__device__ __forceinline__ u64 pack2(float lo, float hi) {
    u64 r;
    asm("mov.b64 %0, {%1, %2};" : "=l"(r) : "f"(lo), "f"(hi));
    return r;
}
__device__ __forceinline__ void unpack2(u64 v, float& lo, float& hi) {
    asm("mov.b64 {%0, %1}, %2;" : "=f"(lo), "=f"(hi) : "l"(v));
}
// d = a * b + d  (two fp32 FMAs in one issue slot)
__device__ __forceinline__ void ffma2(u64& d, u64 a, u64 b) {
    asm("fma.rn.f32x2 %0, %1, %2, %0;" : "+l"(d) : "l"(a), "l"(b));
}

// ---------------- shared GEMM building blocks ----------------
// Tile: 64 edges per block, 256 threads.
// GEMM1 (X[64,IN] @ W1[IN,128] -> silu -> Hs[64,128]): micro-tile 4 edges x 8 hid, f32x2 packed.
template <int IN>
__device__ __forceinline__ void gemm1_silu(const float* Xs, const float* __restrict__ W1,
                                           float* Hs, int t) {
    const int eg = t >> 4;   // 16 groups of 4 edges
    const int hg = t & 15;   // 16 groups of 8 hidden
    u64 acc[4][4];
#pragma unroll
    for (int i = 0; i < 4; i++)
#pragma unroll
        for (int j = 0; j < 4; j++) acc[i][j] = 0ULL;
#pragma unroll 4
    for (int k = 0; k < IN; k++) {
        const float4 wa = *reinterpret_cast<const float4*>(W1 + k * 128 + hg * 8);
        const float4 wb = *reinterpret_cast<const float4*>(W1 + k * 128 + hg * 8 + 4);
        const u64 w0 = pack2(wa.x, wa.y), w1 = pack2(wa.z, wa.w);
        const u64 w2 = pack2(wb.x, wb.y), w3 = pack2(wb.z, wb.w);
#pragma unroll
        for (int i = 0; i < 4; i++) {
            const float x = Xs[(eg * 4 + i) * IN + k];
            const u64 xx = pack2(x, x);
            ffma2(acc[i][0], xx, w0);
            ffma2(acc[i][1], xx, w1);
            ffma2(acc[i][2], xx, w2);
            ffma2(acc[i][3], xx, w3);
        }
    }
#pragma unroll
    for (int i = 0; i < 4; i++)
#pragma unroll
        for (int j = 0; j < 4; j++) {
            float lo, hi;
            unpack2(acc[i][j], lo, hi);
            float* hp = &Hs[(eg * 4 + i) * 128 + hg * 8 + 2 * j];
            hp[0] = silu_f(lo);
            hp[1] = silu_f(hi);
        }
}

// Load 64 x IN tile into smem; X = [Xa (width WA) | Xb (width IN-WA)], zero-pad tail edges.
template <int IN, int WA>
__device__ __forceinline__ void load_xs(float* Xs, const float* __restrict__ Xa,
                                        const float* __restrict__ Xb, int e0, int E, int t) {
    for (int idx = t; idx < 64 * IN; idx += 256) {
        const int le = idx / IN;
        const int c = idx - le * IN;
        const int e = e0 + le;
        float v = 0.f;
        if (e < E) {
            if (c < WA) v = Xa[e * WA + c];
            else        v = Xb[e * (IN - WA) + (c - WA)];
        }
        Xs[idx] = v;
    }
}

// ---------------- generic 2-layer MLP kernel: Y = silu(X@W1)@W2 ----------------
// EPI 0: plain store.  EPI 1: lat blend  g_lat = C_OLD*g_lat + A_C_OLD*cut*val
template <int IN, int WA, int OUT, int EPI>
__global__ void __launch_bounds__(256)
k_mlp(const float* __restrict__ Xa, const float* __restrict__ Xb,
      const float* __restrict__ W1, const float* __restrict__ W2,
      float* __restrict__ Y, int E) {
    extern __shared__ float sm[];
    float* Xs = sm;
    float* Hs = sm + 64 * IN;
    const int t = threadIdx.x;
    const int e0 = blockIdx.x * 64;

    load_xs<IN, WA>(Xs, Xa, Xb, e0, E, t);
    __syncthreads();
    gemm1_silu<IN>(Xs, W1, Hs, t);
    __syncthreads();

    constexpr int OPT = (OUT >= 32) ? 8 : 4;
    constexpr int NOG = OUT / OPT;           // 128->16, 64->8, 32->4, 16->4
    constexpr int EPT = (NOG >= 4) ? NOG / 4 : 1;
    constexpr int OP2 = OPT / 2;
    const int og = t % NOG;
    const int eg = t / NOG;

    u64 acc[EPT][OP2];
#pragma unroll
    for (int i = 0; i < EPT; i++)
#pragma unroll
        for (int j = 0; j < OP2; j++) acc[i][j] = 0ULL;

#pragma unroll 4
    for (int k = 0; k < 128; k++) {
        const float* wr = W2 + k * OUT + og * OPT;
        u64 w[OP2];
        {
            float4 t0 = *reinterpret_cast<const float4*>(wr);
            w[0] = pack2(t0.x, t0.y);
            w[1] = pack2(t0.z, t0.w);
            if (OPT == 8) {
                float4 t1 = *reinterpret_cast<const float4*>(wr + 4);
                w[2] = pack2(t1.x, t1.y);
                w[3] = pack2(t1.z, t1.w);
            }
        }
#pragma unroll
        for (int i = 0; i < EPT; i++) {
            const float h = Hs[(eg * EPT + i) * 128 + k];
            const u64 hh = pack2(h, h);
#pragma unroll
            for (int j = 0; j < OP2; j++) ffma2(acc[i][j], hh, w[j]);
        }
    }

#pragma unroll
    for (int i = 0; i < EPT; i++) {
        const int e = e0 + eg * EPT + i;
        if (e >= E) continue;
        if (EPI == 0) {
#pragma unroll
            for (int j = 0; j < OP2; j++) {
                float lo, hi;
                unpack2(acc[i][j], lo, hi);
                Y[e * OUT + og * OPT + 2 * j + 0] = lo;
                Y[e * OUT + og * OPT + 2 * j + 1] = hi;
            }
        } else {
            const float ac = A_C_OLD * g_cut[e];
#pragma unroll
            for (int j = 0; j < OP2; j++) {
                float lo, hi;
                unpack2(acc[i][j], lo, hi);
                const int o = og * OPT + 2 * j;
                g_lat[e * 128 + o + 0] = C_OLD * g_lat[e * 128 + o + 0] + ac * lo;
                g_lat[e * 128 + o + 1] = C_OLD * g_lat[e * 128 + o + 1] + ac * hi;
            }
        }
    }
}

// ---------------- first stage: gather x2b + MLP(16->128->128) * cut ----------------
__global__ void __launch_bounds__(256)
k_first(const float* __restrict__ node_attrs, const float* __restrict__ edge_embed,
        const float* __restrict__ edge_u, const int* __restrict__ edge_index,
        const float* __restrict__ W1, const float* __restrict__ W2, int E) {
    extern __shared__ float sm[];
    float* Xs = sm;             // 64 x 16
    float* Hs = sm + 64 * 16;   // 64 x 128
    const int t = threadIdx.x;
    const int e0 = blockIdx.x * 64;

    for (int idx = t; idx < 64 * 16; idx += 256) {
        const int le = idx >> 4, c = idx & 15;
        const int e = e0 + le;
        float v = 0.f;
        if (e < E) {
            if (c < 4)       v = node_attrs[edge_index[e] * 4 + c];
            else if (c < 8)  v = node_attrs[edge_index[E + e] * 4 + (c - 4)];
            else             v = edge_embed[e * 8 + (c - 8)];
        }
        Xs[idx] = v;
    }
    if (t < 64) {
        const int e = e0 + t;
        if (e < E) {
            const float u = edge_u[e];
            const float u2 = u * u, u3 = u2 * u, u6 = u3 * u3;
            const float f = 1.f - 28.f * u6 + 48.f * u6 * u - 21.f * u6 * u2;
            g_cut[e] = (u < 1.f) ? f : 0.f;
        }
    }
    __syncthreads();
    gemm1_silu<16>(Xs, W1, Hs, t);
    __syncthreads();

    const int eg = t >> 4, og = t & 15;
    u64 acc[4][4];
#pragma unroll
    for (int i = 0; i < 4; i++)
#pragma unroll
        for (int j = 0; j < 4; j++) acc[i][j] = 0ULL;
#pragma unroll 4
    for (int k = 0; k < 128; k++) {
        const float4 wa = *reinterpret_cast<const float4*>(W2 + k * 128 + og * 8);
        const float4 wb = *reinterpret_cast<const float4*>(W2 + k * 128 + og * 8 + 4);
        const u64 w0 = pack2(wa.x, wa.y), w1 = pack2(wa.z, wa.w);
        const u64 w2 = pack2(wb.x, wb.y), w3 = pack2(wb.z, wb.w);
#pragma unroll
        for (int i = 0; i < 4; i++) {
            const float h = Hs[(eg * 4 + i) * 128 + k];
            const u64 hh = pack2(h, h);
            ffma2(acc[i][0], hh, w0);
            ffma2(acc[i][1], hh, w1);
            ffma2(acc[i][2], hh, w2);
            ffma2(acc[i][3], hh, w3);
        }
    }
#pragma unroll
    for (int i = 0; i < 4; i++) {
        const int e = e0 + eg * 4 + i;
        if (e >= E) continue;
        const float cc = g_cut[e];
#pragma unroll
        for (int j = 0; j < 4; j++) {
            float lo, hi;
            unpack2(acc[i][j], lo, hi);
            g_lat[e * 128 + og * 8 + 2 * j + 0] = cc * lo;
            g_lat[e * 128 + og * 8 + 2 * j + 1] = cc * hi;
        }
    }
}

// ---------------- weighter for fs/fv (from w0[:, :32]) ----------------
__global__ void k_weighter(const float* __restrict__ edge_attr, int E) {
    const int idx = blockIdx.x * blockDim.x + threadIdx.x;
    if (idx >= E * 16) return;
    const int e = idx >> 4, u = idx & 15;
    const float ws = g_w0[e * 64 + 2 * u];
    const float wv = g_w0[e * 64 + 2 * u + 1];
    const float a1 = edge_attr[e * 4 + 1], a2 = edge_attr[e * 4 + 2], a3 = edge_attr[e * 4 + 3];
    g_fs[e * 16 + u] = ws * edge_attr[e * 4 + 0];
    g_fv[e * 48 + u * 3 + 0] = wv * a1;
    g_fv[e * 48 + u * 3 + 1] = wv * a2;
    g_fv[e * 48 + u * 3 + 2] = wv * a3;
}

// ---------------- segment-sum scatter of env weights ----------------
__global__ void k_scatter(const float* __restrict__ wenv, int stride, int off,
                          const float* __restrict__ edge_attr,
                          const int* __restrict__ edge_index, int E) {
    const int idx = blockIdx.x * blockDim.x + threadIdx.x;
    if (idx >= E * 16) return;
    const int e = idx >> 4, u = idx & 15;
    const int c = edge_index[e];  // center
    const float ws = wenv[e * stride + off + 2 * u];
    const float wv = wenv[e * stride + off + 2 * u + 1];
    atomicAdd(&g_env_s[c * 16 + u], ws * edge_attr[e * 4 + 0]);
    atomicAdd(&g_env_v[c * 48 + u * 3 + 0], wv * edge_attr[e * 4 + 1]);
    atomicAdd(&g_env_v[c * 48 + u * 3 + 1], wv * edge_attr[e * 4 + 2]);
    atomicAdd(&g_env_v[c * 48 + u * 3 + 2], wv * edge_attr[e * 4 + 3]);
}

// ---------------- per-node 16x16 env linears (norm * inv_sm folded in) ----------------
__global__ void k_envlin(const float* __restrict__ Ws, const float* __restrict__ Wv, int N) {
    const int idx = blockIdx.x * blockDim.x + threadIdx.x;
    if (idx >= N * 16) return;
    const int n = idx >> 4, v = idx & 15;
    float s = 0.f, v0 = 0.f, v1 = 0.f, v2 = 0.f;
#pragma unroll
    for (int u = 0; u < 16; u++) {
        const float wsv = Ws[u * 16 + v];
        const float wvv = Wv[u * 16 + v];
        s  = fmaf(g_env_s[n * 16 + u], wsv, s);
        v0 = fmaf(g_env_v[n * 48 + u * 3 + 0], wvv, v0);
        v1 = fmaf(g_env_v[n * 48 + u * 3 + 1], wvv, v1);
        v2 = fmaf(g_env_v[n * 48 + u * 3 + 2], wvv, v2);
    }
    g_env_s2[n * 16 + v] = s * NORM_LIN;
    g_env_v2[n * 48 + v * 3 + 0] = v0 * NORM_LIN;
    g_env_v2[n * 48 + v * 3 + 1] = v1 * NORM_LIN;
    g_env_v2[n * 48 + v * 3 + 2] = v2 * NORM_LIN;
}

// ---------------- per-edge combine: s1,s2 and V = [v1,v2,v3] ----------------
__global__ void k_combine(const int* __restrict__ edge_index, int E) {
    const int idx = blockIdx.x * blockDim.x + threadIdx.x;
    if (idx >= E * 16) return;
    const int e = idx >> 4, u = idx & 15;
    const int c = edge_index[e];
    const float es  = g_env_s2[c * 16 + u];
    const float ev0 = g_env_v2[c * 48 + u * 3 + 0];
    const float ev1 = g_env_v2[c * 48 + u * 3 + 1];
    const float ev2 = g_env_v2[c * 48 + u * 3 + 2];
    const float fsv = g_fs[e * 16 + u];
    const float fv0 = g_fv[e * 48 + u * 3 + 0];
    const float fv1 = g_fv[e * 48 + u * 3 + 1];
    const float fv2 = g_fv[e * 48 + u * 3 + 2];

    g_scal[e * 32 + 2 * u]     = fsv * es;
    g_scal[e * 32 + 2 * u + 1] = (fv0 * ev0 + fv1 * ev1 + fv2 * ev2) * INV_S3;

    float* Vp = &g_V[e * 144];
    Vp[u * 3 + 0] = fsv * ev0;          // v1
    Vp[u * 3 + 1] = fsv * ev1;
    Vp[u * 3 + 2] = fsv * ev2;
    Vp[48 + u * 3 + 0] = fv0 * es;      // v2
    Vp[48 + u * 3 + 1] = fv1 * es;
    Vp[48 + u * 3 + 2] = fv2 * es;
    Vp[96 + u * 3 + 0] = (fv1 * ev2 - fv2 * ev1) * INV_S2;  // v3 = fv x ev
    Vp[96 + u * 3 + 1] = (fv2 * ev0 - fv0 * ev2) * INV_S2;
    Vp[96 + u * 3 + 2] = (fv0 * ev1 - fv1 * ev0) * INV_S2;
}

// ---------------- fused l2w MLP (160->128->1280) + bilinear contraction ----------------
// Never materializes lw in HBM: Hs @ W2 is computed 128 columns at a time into smem,
// immediately contracted with S (in Xs scal region) / V (global, L1-cached).
__global__ void __launch_bounds__(256)
k_l2w(const float* __restrict__ W1, const float* __restrict__ W2, int E) {
    extern __shared__ float sm[];
    float* Xs = sm;                  // 64 x 160
    float* Hs = Xs + 64 * 160;       // 64 x 128
    float* Ls = Hs + 64 * 128;       // 64 x 128 (lw column chunk)
    const int t = threadIdx.x;
    const int e0 = blockIdx.x * 64;

    load_xs<160, 128>(Xs, g_lat, g_scal, e0, E, t);
    __syncthreads();
    gemm1_silu<160>(Xs, W1, Hs, t);
    __syncthreads();

    const int eg = t >> 4;   // 4 edges per thread (both phases)
    const int vv = t & 15;   // contraction output column v

    float facc[4] = {0.f, 0.f, 0.f, 0.f};
    float vacc[4][3] = {};

#pragma unroll 1
    for (int ch = 0; ch < 10; ch++) {
        // GEMM: Ls[64,128] = Hs @ W2[:, ch*128 : ch*128+128]
        u64 acc[4][4];
#pragma unroll
        for (int i = 0; i < 4; i++)
#pragma unroll
            for (int j = 0; j < 4; j++) acc[i][j] = 0ULL;
#pragma unroll 4
        for (int k = 0; k < 128; k++) {
            const float* wr = W2 + k * 1280 + ch * 128 + vv * 8;
            const float4 wa = *reinterpret_cast<const float4*>(wr);
            const float4 wb = *reinterpret_cast<const float4*>(wr + 4);
            const u64 w0 = pack2(wa.x, wa.y), w1 = pack2(wa.z, wa.w);
            const u64 w2 = pack2(wb.x, wb.y), w3 = pack2(wb.z, wb.w);
#pragma unroll
            for (int i = 0; i < 4; i++) {
                const float h = Hs[(eg * 4 + i) * 128 + k];
                const u64 hh = pack2(h, h);
                ffma2(acc[i][0], hh, w0);
                ffma2(acc[i][1], hh, w1);
                ffma2(acc[i][2], hh, w2);
                ffma2(acc[i][3], hh, w3);
            }
        }
        __syncthreads();  // previous chunk's contraction done reading Ls
#pragma unroll
        for (int i = 0; i < 4; i++)
#pragma unroll
            for (int j = 0; j < 4; j++) {
                float lo, hi;
                unpack2(acc[i][j], lo, hi);
                float* lp = &Ls[(eg * 4 + i) * 128 + vv * 8 + 2 * j];
                lp[0] = lo;
                lp[1] = hi;
            }
        __syncthreads();  // Ls ready

        // contraction: 8 (p,u) rows in this chunk; lw[e, pu*16+v]
#pragma unroll
        for (int r = 0; r < 8; r++) {
            const int pu = ch * 8 + r;
#pragma unroll
            for (int i = 0; i < 4; i++) {
                const int el = eg * 4 + i;
                const float val = Ls[el * 128 + r * 16 + vv];
                if (pu < 32) {  // ws block: S[e,p,u] lives in Xs scal region
                    const int p = pu >> 4, u = pu & 15;
                    facc[i] = fmaf(Xs[el * 160 + 128 + 2 * u + p], val, facc[i]);
                } else {        // wv block: V from global (L1 broadcast across v threads)
                    const int q = pu - 32;
                    const int p = q >> 4, u = q & 15;
                    const int e = e0 + el;
                    if (e < E) {
                        const float* vp = &g_V[e * 144 + p * 48 + u * 3];
                        vacc[i][0] = fmaf(vp[0], val, vacc[i][0]);
                        vacc[i][1] = fmaf(vp[1], val, vacc[i][1]);
                        vacc[i][2] = fmaf(vp[2], val, vacc[i][2]);
                    }
                }
            }
        }
    }

#pragma unroll
    for (int i = 0; i < 4; i++) {
        const int e = e0 + eg * 4 + i;
        if (e >= E) continue;
        g_fs[e * 16 + vv] = C_FS * facc[i];
        g_fv[e * 48 + vv * 3 + 0] = C_FV * vacc[i][0];
        g_fv[e * 48 + vv * 3 + 1] = C_FV * vacc[i][1];
        g_fv[e * 48 + vv * 3 + 2] = C_FV * vacc[i][2];
    }
}

// ---------------- final output: out[e,i] = inv_sm * sum_u fw[e,u] * fv[e,u,i] ----------------
__global__ void k_out(float* __restrict__ out, int E) {
    const int idx = blockIdx.x * blockDim.x + threadIdx.x;
    if (idx >= E * 3) return;
    const int e = idx / 3, i = idx - e * 3;
    float acc = 0.f;
#pragma unroll
    for (int u = 0; u < 16; u++)
        acc = fmaf(g_wenv1[e * 16 + u], g_fv[e * 48 + u * 3 + i], acc);
    out[idx] = INV_SM * acc;
}

// ---------------- host driver ----------------
extern "C" void kernel_launch(void* const* d_in, const int* in_sizes, int n_in,
                              void* d_out, int out_size) {
    const float* edge_attr  = (const float*)d_in[0];
    const float* node_attrs = (const float*)d_in[1];
    const float* edge_embed = (const float*)d_in[2];
    const float* edge_u     = (const float*)d_in[3];
    const int*   edge_index = (const int*)d_in[4];
    const float* w2b1    = (const float*)d_in[5];
    const float* w2b2    = (const float*)d_in[6];
    const float* lat1_w1 = (const float*)d_in[7];
    const float* lat1_w2 = (const float*)d_in[8];
    const float* env0_w1 = (const float*)d_in[9];
    const float* env0_w2 = (const float*)d_in[10];
    const float* env1_w1 = (const float*)d_in[11];
    const float* env1_w2 = (const float*)d_in[12];
    const float* l2w0_w1 = (const float*)d_in[13];
    const float* l2w0_w2 = (const float*)d_in[14];
    const float* l2w1_w1 = (const float*)d_in[15];
    const float* l2w1_w2 = (const float*)d_in[16];
    const float* envlin_ws = (const float*)d_in[17];
    const float* envlin_wv = (const float*)d_in[18];
    const float* fl2w_w1 = (const float*)d_in[19];
    const float* fl2w_w2 = (const float*)d_in[20];
    float* out = (float*)d_out;

    const int E = in_sizes[0] / 4;
    const int N = in_sizes[1] / 4;
    if (E > MAX_E || N > MAX_N) return;

    float *p_lat, *p_scal, *p_w0, *p_wenv1, *p_env_s, *p_env_v;
    cudaGetSymbolAddress((void**)&p_lat, g_lat);
    cudaGetSymbolAddress((void**)&p_scal, g_scal);
    cudaGetSymbolAddress((void**)&p_w0, g_w0);
    cudaGetSymbolAddress((void**)&p_wenv1, g_wenv1);
    cudaGetSymbolAddress((void**)&p_env_s, g_env_s);
    cudaGetSymbolAddress((void**)&p_env_v, g_env_v);

    const size_t smA = (64 * 16 + 64 * 128) * sizeof(float);              // 36 KB
    const size_t smB = (64 * 128 + 64 * 128) * sizeof(float);             // 64 KB
    const size_t smC = (64 * 160 + 64 * 128) * sizeof(float);             // 72 KB
    const size_t smL = (64 * 160 + 64 * 128 + 64 * 128) * sizeof(float);  // 104 KB

    cudaFuncSetAttribute((const void*)k_first, cudaFuncAttributeMaxDynamicSharedMemorySize, (int)smA);
    cudaFuncSetAttribute((const void*)k_mlp<128,128,64,0>,  cudaFuncAttributeMaxDynamicSharedMemorySize, (int)smB);
    cudaFuncSetAttribute((const void*)k_mlp<128,128,32,0>,  cudaFuncAttributeMaxDynamicSharedMemorySize, (int)smB);
    cudaFuncSetAttribute((const void*)k_mlp<160,128,128,1>, cudaFuncAttributeMaxDynamicSharedMemorySize, (int)smC);
    cudaFuncSetAttribute((const void*)k_mlp<160,128,16,0>,  cudaFuncAttributeMaxDynamicSharedMemorySize, (int)smC);
    cudaFuncSetAttribute((const void*)k_l2w,                cudaFuncAttributeMaxDynamicSharedMemorySize, (int)smL);

    const int nb   = (E + 63) / 64;
    const int nb16 = (E * 16 + 255) / 256;

    // stage 0: x2b gather + MLP + cut
    k_first<<<nb, 256, smA>>>(node_attrs, edge_embed, edge_u, edge_index, w2b1, w2b2, E);
    // env0 MLP -> w0 (w_edge | w_env)
    k_mlp<128,128,64,0><<<nb, 256, smB>>>(p_lat, p_lat, env0_w1, env0_w2, p_w0, E);
    k_weighter<<<nb16, 256>>>(edge_attr, E);

    // ---- layer 0 ----
    cudaMemsetAsync(p_env_s, 0, (size_t)N * 16 * sizeof(float));
    cudaMemsetAsync(p_env_v, 0, (size_t)N * 48 * sizeof(float));
    k_scatter<<<nb16, 256>>>(p_w0, 64, 32, edge_attr, edge_index, E);
    k_envlin<<<(N * 16 + 255) / 256, 256>>>(envlin_ws, envlin_wv, N);
    k_combine<<<nb16, 256>>>(edge_index, E);
    k_l2w<<<nb, 256, smL>>>(l2w0_w1, l2w0_w2, E);

    // ---- layer 1 ----
    k_mlp<160,128,128,1><<<nb, 256, smC>>>(p_lat, p_scal, lat1_w1, lat1_w2, p_lat, E);  // lat blend
    k_mlp<128,128,32,0><<<nb, 256, smB>>>(p_lat, p_lat, env1_w1, env1_w2, p_wenv1, E);
    cudaMemsetAsync(p_env_s, 0, (size_t)N * 16 * sizeof(float));
    cudaMemsetAsync(p_env_v, 0, (size_t)N * 48 * sizeof(float));
    k_scatter<<<nb16, 256>>>(p_wenv1, 32, 0, edge_attr, edge_index, E);
    k_envlin<<<(N * 16 + 255) / 256, 256>>>(envlin_ws + 256, envlin_wv + 256, N);
    k_combine<<<nb16, 256>>>(edge_index, E);
    k_l2w<<<nb, 256, smL>>>(l2w1_w1, l2w1_w2, E);

    // ---- final: fw MLP + contraction with fv ----
    k_mlp<160,128,16,0><<<nb, 256, smC>>>(p_lat, p_scal, fl2w_w1, fl2w_w2, p_wenv1, E);
    k_out<<<(E * 3 + 255) / 256, 256>>>(out, E);
}

// round 4
// speedup vs baseline: 1.7164x; 1.4947x over previous
#include <cuda_runtime.h>
#include <cstdint>

// ---------------- problem constants ----------------
#define MAX_E 120000
#define MAX_N 5000

typedef unsigned long long u64;

// ---------------- scratch (static __device__, allocation-free) ----------------
__device__ float g_cut[MAX_E];
__device__ float g_lat[MAX_E * 128];
__device__ float g_w0[MAX_E * 64];
__device__ float g_wenv1[MAX_E * 32];
__device__ float g_fs[MAX_E * 16];
__device__ float g_fv[MAX_E * 48];
__device__ float g_scal[MAX_E * 32];
__device__ float g_V[MAX_E * 144];
__device__ float g_env_s[MAX_N * 16];
__device__ float g_env_v[MAX_N * 48];
__device__ float g_env_s2[MAX_N * 16];
__device__ float g_env_v2[MAX_N * 48];
__device__ float g_w1t[128 * 160];     // transposed l2w W1: [n=128][k=160], tf32-rounded
__device__ float g_w2t[1280 * 128];    // transposed l2w W2: [n=1280][k=128], tf32-rounded

// ---------------- math constants ----------------
constexpr float C_OLD    = 0.8944271909999159f;
constexpr float A_C_OLD  = 0.4472135954999579f;
constexpr float INV_S3   = 0.5773502691896258f;
constexpr float INV_S2   = 0.7071067811865476f;
constexpr float C_FS     = 0.17677669529663687f;
constexpr float C_FV     = 0.14433756729740643f;
constexpr float NORM_LIN = 0.05590169943749474f;
constexpr float INV_SM   = 0.25f;

__device__ __forceinline__ float silu_f(float x) { return x / (1.f + __expf(-x)); }

// ---------------- packed f32x2 helpers ----------------
__device__ __forceinline__ u64 pack2(float lo, float hi) {
    u64 r;
    asm("mov.b64 %0, {%1, %2};" : "=l"(r) : "f"(lo), "f"(hi));
    return r;
}
__device__ __forceinline__ void unpack2(u64 v, float& lo, float& hi) {
    asm("mov.b64 {%0, %1}, %2;" : "=f"(lo), "=f"(hi) : "l"(v));
}
__device__ __forceinline__ void ffma2(u64& d, u64 a, u64 b) {
    asm("fma.rn.f32x2 %0, %1, %2, %0;" : "+l"(d) : "l"(a), "l"(b));
}

// ---------------- tf32 helpers ----------------
__device__ __forceinline__ float tf32r(float x) {
    uint32_t u;
    asm("cvt.rna.tf32.f32 %0, %1;" : "=r"(u) : "f"(x));
    return __uint_as_float(u);
}
// D(16x8) += A(16x8,row) * B(8x8,col)   [tf32 in, f32 out]
__device__ __forceinline__ void mma_tf32(float& d0, float& d1, float& d2, float& d3,
                                         uint32_t a0, uint32_t a1, uint32_t a2, uint32_t a3,
                                         uint32_t b0, uint32_t b1) {
    asm volatile(
        "mma.sync.aligned.m16n8k8.row.col.f32.tf32.tf32.f32 "
        "{%0,%1,%2,%3}, {%4,%5,%6,%7}, {%8,%9}, {%0,%1,%2,%3};"
        : "+f"(d0), "+f"(d1), "+f"(d2), "+f"(d3)
        : "r"(a0), "r"(a1), "r"(a2), "r"(a3), "r"(b0), "r"(b1));
}
__device__ __forceinline__ uint32_t fbits(float x) { return __float_as_uint(x); }

// ---------------- scalar GEMM building blocks (proven in R2) ----------------
template <int IN>
__device__ __forceinline__ void gemm1_silu(const float* Xs, const float* __restrict__ W1,
                                           float* Hs, int t) {
    const int eg = t >> 4;
    const int hg = t & 15;
    u64 acc[4][4];
#pragma unroll
    for (int i = 0; i < 4; i++)
#pragma unroll
        for (int j = 0; j < 4; j++) acc[i][j] = 0ULL;
#pragma unroll 4
    for (int k = 0; k < IN; k++) {
        const float4 wa = *reinterpret_cast<const float4*>(W1 + k * 128 + hg * 8);
        const float4 wb = *reinterpret_cast<const float4*>(W1 + k * 128 + hg * 8 + 4);
        const u64 w0 = pack2(wa.x, wa.y), w1 = pack2(wa.z, wa.w);
        const u64 w2 = pack2(wb.x, wb.y), w3 = pack2(wb.z, wb.w);
#pragma unroll
        for (int i = 0; i < 4; i++) {
            const float x = Xs[(eg * 4 + i) * IN + k];
            const u64 xx = pack2(x, x);
            ffma2(acc[i][0], xx, w0);
            ffma2(acc[i][1], xx, w1);
            ffma2(acc[i][2], xx, w2);
            ffma2(acc[i][3], xx, w3);
        }
    }
#pragma unroll
    for (int i = 0; i < 4; i++)
#pragma unroll
        for (int j = 0; j < 4; j++) {
            float lo, hi;
            unpack2(acc[i][j], lo, hi);
            float* hp = &Hs[(eg * 4 + i) * 128 + hg * 8 + 2 * j];
            hp[0] = silu_f(lo);
            hp[1] = silu_f(hi);
        }
}

template <int IN, int WA>
__device__ __forceinline__ void load_xs(float* Xs, const float* __restrict__ Xa,
                                        const float* __restrict__ Xb, int e0, int E, int t) {
    for (int idx = t; idx < 64 * IN; idx += 256) {
        const int le = idx / IN;
        const int c = idx - le * IN;
        const int e = e0 + le;
        float v = 0.f;
        if (e < E) {
            if (c < WA) v = Xa[e * WA + c];
            else        v = Xb[e * (IN - WA) + (c - WA)];
        }
        Xs[idx] = v;
    }
}

template <int IN, int WA, int OUT, int EPI>
__global__ void __launch_bounds__(256)
k_mlp(const float* __restrict__ Xa, const float* __restrict__ Xb,
      const float* __restrict__ W1, const float* __restrict__ W2,
      float* __restrict__ Y, int E) {
    extern __shared__ float sm[];
    float* Xs = sm;
    float* Hs = sm + 64 * IN;
    const int t = threadIdx.x;
    const int e0 = blockIdx.x * 64;

    load_xs<IN, WA>(Xs, Xa, Xb, e0, E, t);
    __syncthreads();
    gemm1_silu<IN>(Xs, W1, Hs, t);
    __syncthreads();

    constexpr int OPT = (OUT >= 32) ? 8 : 4;
    constexpr int NOG = OUT / OPT;
    constexpr int EPT = (64 * NOG) / 256;
    constexpr int OP2 = OPT / 2;
    const int og = t % NOG;
    const int eg = t / NOG;

    u64 acc[EPT][OP2];
#pragma unroll
    for (int i = 0; i < EPT; i++)
#pragma unroll
        for (int j = 0; j < OP2; j++) acc[i][j] = 0ULL;

#pragma unroll 4
    for (int k = 0; k < 128; k++) {
        const float* wr = W2 + k * OUT + og * OPT;
        u64 w[OP2];
        {
            float4 t0 = *reinterpret_cast<const float4*>(wr);
            w[0] = pack2(t0.x, t0.y);
            w[1] = pack2(t0.z, t0.w);
            if (OPT == 8) {
                float4 t1 = *reinterpret_cast<const float4*>(wr + 4);
                w[2] = pack2(t1.x, t1.y);
                w[3] = pack2(t1.z, t1.w);
            }
        }
#pragma unroll
        for (int i = 0; i < EPT; i++) {
            const float h = Hs[(eg * EPT + i) * 128 + k];
            const u64 hh = pack2(h, h);
#pragma unroll
            for (int j = 0; j < OP2; j++) ffma2(acc[i][j], hh, w[j]);
        }
    }

#pragma unroll
    for (int i = 0; i < EPT; i++) {
        const int e = e0 + eg * EPT + i;
        if (e >= E) continue;
        if (EPI == 0) {
#pragma unroll
            for (int j = 0; j < OP2; j++) {
                float lo, hi;
                unpack2(acc[i][j], lo, hi);
                Y[e * OUT + og * OPT + 2 * j + 0] = lo;
                Y[e * OUT + og * OPT + 2 * j + 1] = hi;
            }
        } else {
            const float ac = A_C_OLD * g_cut[e];
#pragma unroll
            for (int j = 0; j < OP2; j++) {
                float lo, hi;
                unpack2(acc[i][j], lo, hi);
                const int o = og * OPT + 2 * j;
                g_lat[e * 128 + o + 0] = C_OLD * g_lat[e * 128 + o + 0] + ac * lo;
                g_lat[e * 128 + o + 1] = C_OLD * g_lat[e * 128 + o + 1] + ac * hi;
            }
        }
    }
}

// ---------------- first stage ----------------
__global__ void __launch_bounds__(256)
k_first(const float* __restrict__ node_attrs, const float* __restrict__ edge_embed,
        const float* __restrict__ edge_u, const int* __restrict__ edge_index,
        const float* __restrict__ W1, const float* __restrict__ W2, int E) {
    extern __shared__ float sm[];
    float* Xs = sm;
    float* Hs = sm + 64 * 16;
    const int t = threadIdx.x;
    const int e0 = blockIdx.x * 64;

    for (int idx = t; idx < 64 * 16; idx += 256) {
        const int le = idx >> 4, c = idx & 15;
        const int e = e0 + le;
        float v = 0.f;
        if (e < E) {
            if (c < 4)       v = node_attrs[edge_index[e] * 4 + c];
            else if (c < 8)  v = node_attrs[edge_index[E + e] * 4 + (c - 4)];
            else             v = edge_embed[e * 8 + (c - 8)];
        }
        Xs[idx] = v;
    }
    if (t < 64) {
        const int e = e0 + t;
        if (e < E) {
            const float u = edge_u[e];
            const float u2 = u * u, u3 = u2 * u, u6 = u3 * u3;
            const float f = 1.f - 28.f * u6 + 48.f * u6 * u - 21.f * u6 * u2;
            g_cut[e] = (u < 1.f) ? f : 0.f;
        }
    }
    __syncthreads();
    gemm1_silu<16>(Xs, W1, Hs, t);
    __syncthreads();

    const int eg = t >> 4, og = t & 15;
    u64 acc[4][4];
#pragma unroll
    for (int i = 0; i < 4; i++)
#pragma unroll
        for (int j = 0; j < 4; j++) acc[i][j] = 0ULL;
#pragma unroll 4
    for (int k = 0; k < 128; k++) {
        const float4 wa = *reinterpret_cast<const float4*>(W2 + k * 128 + og * 8);
        const float4 wb = *reinterpret_cast<const float4*>(W2 + k * 128 + og * 8 + 4);
        const u64 w0 = pack2(wa.x, wa.y), w1 = pack2(wa.z, wa.w);
        const u64 w2 = pack2(wb.x, wb.y), w3 = pack2(wb.z, wb.w);
#pragma unroll
        for (int i = 0; i < 4; i++) {
            const float h = Hs[(eg * 4 + i) * 128 + k];
            const u64 hh = pack2(h, h);
            ffma2(acc[i][0], hh, w0);
            ffma2(acc[i][1], hh, w1);
            ffma2(acc[i][2], hh, w2);
            ffma2(acc[i][3], hh, w3);
        }
    }
#pragma unroll
    for (int i = 0; i < 4; i++) {
        const int e = e0 + eg * 4 + i;
        if (e >= E) continue;
        const float cc = g_cut[e];
#pragma unroll
        for (int j = 0; j < 4; j++) {
            float lo, hi;
            unpack2(acc[i][j], lo, hi);
            g_lat[e * 128 + og * 8 + 2 * j + 0] = cc * lo;
            g_lat[e * 128 + og * 8 + 2 * j + 1] = cc * hi;
        }
    }
}

// ---------------- small per-edge / per-node kernels ----------------
__global__ void k_weighter(const float* __restrict__ edge_attr, int E) {
    const int idx = blockIdx.x * blockDim.x + threadIdx.x;
    if (idx >= E * 16) return;
    const int e = idx >> 4, u = idx & 15;
    const float ws = g_w0[e * 64 + 2 * u];
    const float wv = g_w0[e * 64 + 2 * u + 1];
    g_fs[e * 16 + u] = ws * edge_attr[e * 4 + 0];
    g_fv[e * 48 + u * 3 + 0] = wv * edge_attr[e * 4 + 1];
    g_fv[e * 48 + u * 3 + 1] = wv * edge_attr[e * 4 + 2];
    g_fv[e * 48 + u * 3 + 2] = wv * edge_attr[e * 4 + 3];
}

__global__ void k_scatter(const float* __restrict__ wenv, int stride, int off,
                          const float* __restrict__ edge_attr,
                          const int* __restrict__ edge_index, int E) {
    const int idx = blockIdx.x * blockDim.x + threadIdx.x;
    if (idx >= E * 16) return;
    const int e = idx >> 4, u = idx & 15;
    const int c = edge_index[e];
    const float ws = wenv[e * stride + off + 2 * u];
    const float wv = wenv[e * stride + off + 2 * u + 1];
    atomicAdd(&g_env_s[c * 16 + u], ws * edge_attr[e * 4 + 0]);
    atomicAdd(&g_env_v[c * 48 + u * 3 + 0], wv * edge_attr[e * 4 + 1]);
    atomicAdd(&g_env_v[c * 48 + u * 3 + 1], wv * edge_attr[e * 4 + 2]);
    atomicAdd(&g_env_v[c * 48 + u * 3 + 2], wv * edge_attr[e * 4 + 3]);
}

__global__ void k_envlin(const float* __restrict__ Ws, const float* __restrict__ Wv, int N) {
    const int idx = blockIdx.x * blockDim.x + threadIdx.x;
    if (idx >= N * 16) return;
    const int n = idx >> 4, v = idx & 15;
    float s = 0.f, v0 = 0.f, v1 = 0.f, v2 = 0.f;
#pragma unroll
    for (int u = 0; u < 16; u++) {
        const float wsv = Ws[u * 16 + v];
        const float wvv = Wv[u * 16 + v];
        s  = fmaf(g_env_s[n * 16 + u], wsv, s);
        v0 = fmaf(g_env_v[n * 48 + u * 3 + 0], wvv, v0);
        v1 = fmaf(g_env_v[n * 48 + u * 3 + 1], wvv, v1);
        v2 = fmaf(g_env_v[n * 48 + u * 3 + 2], wvv, v2);
    }
    g_env_s2[n * 16 + v] = s * NORM_LIN;
    g_env_v2[n * 48 + v * 3 + 0] = v0 * NORM_LIN;
    g_env_v2[n * 48 + v * 3 + 1] = v1 * NORM_LIN;
    g_env_v2[n * 48 + v * 3 + 2] = v2 * NORM_LIN;
}

__global__ void k_combine(const int* __restrict__ edge_index, int E) {
    const int idx = blockIdx.x * blockDim.x + threadIdx.x;
    if (idx >= E * 16) return;
    const int e = idx >> 4, u = idx & 15;
    const int c = edge_index[e];
    const float es  = g_env_s2[c * 16 + u];
    const float ev0 = g_env_v2[c * 48 + u * 3 + 0];
    const float ev1 = g_env_v2[c * 48 + u * 3 + 1];
    const float ev2 = g_env_v2[c * 48 + u * 3 + 2];
    const float fsv = g_fs[e * 16 + u];
    const float fv0 = g_fv[e * 48 + u * 3 + 0];
    const float fv1 = g_fv[e * 48 + u * 3 + 1];
    const float fv2 = g_fv[e * 48 + u * 3 + 2];

    g_scal[e * 32 + 2 * u]     = fsv * es;
    g_scal[e * 32 + 2 * u + 1] = (fv0 * ev0 + fv1 * ev1 + fv2 * ev2) * INV_S3;

    float* Vp = &g_V[e * 144];
    Vp[u * 3 + 0] = fsv * ev0;
    Vp[u * 3 + 1] = fsv * ev1;
    Vp[u * 3 + 2] = fsv * ev2;
    Vp[48 + u * 3 + 0] = fv0 * es;
    Vp[48 + u * 3 + 1] = fv1 * es;
    Vp[48 + u * 3 + 2] = fv2 * es;
    Vp[96 + u * 3 + 0] = (fv1 * ev2 - fv2 * ev1) * INV_S2;
    Vp[96 + u * 3 + 1] = (fv2 * ev0 - fv0 * ev2) * INV_S2;
    Vp[96 + u * 3 + 2] = (fv0 * ev1 - fv1 * ev0) * INV_S2;
}

// ---------------- weight transpose + tf32 round ----------------
__global__ void k_transpose(const float* __restrict__ W, float* __restrict__ WT, int R, int C) {
    const int idx = blockIdx.x * blockDim.x + threadIdx.x;
    if (idx >= R * C) return;
    const int r = idx / C, c = idx - r * C;
    WT[c * R + r] = tf32r(W[idx]);
}

// ---------------- mma.sync tf32 fused l2w ----------------
// 128 edges per CTA, 8 warps, warp owns 16 edge rows.
// GEMM1: H = silu(X[128,160] @ W1T^T), accumulators held (16 chunks x 4 regs),
//        H written back into Xs (tf32). B-frags streamed from L1-resident g_w1t.
// GEMM2: A-frags (all 16 k-steps) held in 64 regs; W2T streamed via 2x8.25KB smem
//        double buffer (16 output rows per stage); each D fragment contracted
//        against S (smem) / V (L1) immediately. lw never materialized.
#define XS_STR 162
#define W2_STR 132
#define L2W_SMEM ((128 * XS_STR + 128 * 33 + 2 * 16 * W2_STR) * 4)

__global__ void __launch_bounds__(256, 1)
k_l2w_ts(int E) {
    extern __shared__ float sm[];
    float* Xs  = sm;                        // 128 x 162 (X then H, tf32 values)
    float* Ss  = sm + 128 * XS_STR;         // 128 x 33
    float* W2s = Ss + 128 * 33;             // 2 x (16 x 132)
    const int t = threadIdx.x;
    const int lane = t & 31, w = t >> 5;
    const int g = lane >> 2, q = lane & 3;  // mma group / thread-in-group
    const int e0 = blockIdx.x * 128;

    // stage X (tf32-rounded)
    for (int idx = t; idx < 128 * 160; idx += 256) {
        const int r = idx / 160, c = idx - r * 160;
        const int e = e0 + r;
        float v = 0.f;
        if (e < E) v = (c < 128) ? g_lat[e * 128 + c] : g_scal[e * 32 + (c - 128)];
        Xs[r * XS_STR + c] = tf32r(v);
    }
    // stage S (full fp32), layout [e_loc][pu], pu = p*16+u
    for (int idx = t; idx < 128 * 32; idx += 256) {
        const int el = idx >> 5, pu = idx & 31;
        const int e = e0 + el;
        Ss[el * 33 + pu] = (e < E) ? g_scal[e * 32 + 2 * (pu & 15) + (pu >> 4)] : 0.f;
    }
    __syncthreads();

    const int r0 = w * 16 + g;      // this thread's first local row
    const int er0 = e0 + r0, er8 = er0 + 8;

    // ---- GEMM1: acc[16 chunks][4] over K=160 ----
    {
        float acc[16][4];
#pragma unroll
        for (int c = 0; c < 16; c++)
#pragma unroll
            for (int j = 0; j < 4; j++) acc[c][j] = 0.f;

#pragma unroll 1
        for (int ks = 0; ks < 20; ks++) {
            const int k0 = ks * 8;
            const uint32_t a0 = fbits(Xs[r0 * XS_STR + k0 + q]);
            const uint32_t a1 = fbits(Xs[(r0 + 8) * XS_STR + k0 + q]);
            const uint32_t a2 = fbits(Xs[r0 * XS_STR + k0 + q + 4]);
            const uint32_t a3 = fbits(Xs[(r0 + 8) * XS_STR + k0 + q + 4]);
#pragma unroll
            for (int ch = 0; ch < 16; ch++) {
                const float* wb = &g_w1t[(ch * 8 + g) * 160 + k0 + q];
                const uint32_t b0 = fbits(wb[0]);
                const uint32_t b1 = fbits(wb[4]);
                mma_tf32(acc[ch][0], acc[ch][1], acc[ch][2], acc[ch][3],
                         a0, a1, a2, a3, b0, b1);
            }
        }
        __syncthreads();   // all X reads complete before overwrite
#pragma unroll
        for (int ch = 0; ch < 16; ch++) {
            const int c0 = ch * 8 + 2 * q;
            Xs[r0 * XS_STR + c0]           = tf32r(silu_f(acc[ch][0]));
            Xs[r0 * XS_STR + c0 + 1]       = tf32r(silu_f(acc[ch][1]));
            Xs[(r0 + 8) * XS_STR + c0]     = tf32r(silu_f(acc[ch][2]));
            Xs[(r0 + 8) * XS_STR + c0 + 1] = tf32r(silu_f(acc[ch][3]));
        }
        __syncthreads();
    }

    // ---- GEMM2 A-fragments held in registers (K=128 -> 16 k-steps) ----
    uint32_t Af[16][4];
#pragma unroll
    for (int ks = 0; ks < 16; ks++) {
        const int k0 = ks * 8;
        Af[ks][0] = fbits(Xs[r0 * XS_STR + k0 + q]);
        Af[ks][1] = fbits(Xs[(r0 + 8) * XS_STR + k0 + q]);
        Af[ks][2] = fbits(Xs[r0 * XS_STR + k0 + q + 4]);
        Af[ks][3] = fbits(Xs[(r0 + 8) * XS_STR + k0 + q + 4]);
    }

    // stage W2T rows for pu=0
    {
        const int n = t >> 5, k4 = (t & 31) * 4;  // 8 rows per pass
        for (int nn = n; nn < 16; nn += 8) {
            const float4 v = *reinterpret_cast<const float4*>(&g_w2t[nn * 128 + k4]);
            *reinterpret_cast<float4*>(&W2s[nn * W2_STR + k4]) = v;
        }
    }
    __syncthreads();

    float fs[2][4];
    float fva[2][4][3];
#pragma unroll
    for (int h = 0; h < 2; h++) {
#pragma unroll
        for (int j = 0; j < 4; j++) {
            fs[h][j] = 0.f;
            fva[h][j][0] = 0.f; fva[h][j][1] = 0.f; fva[h][j][2] = 0.f;
        }
    }

#pragma unroll 1
    for (int pu = 0; pu < 80; pu++) {
        float* Wb = W2s + (pu & 1) * (16 * W2_STR);
        // prefetch next stage into other buffer
        if (pu < 79) {
            float* Wn = W2s + ((pu + 1) & 1) * (16 * W2_STR);
            const int n = t >> 5, k4 = (t & 31) * 4;
            for (int nn = n; nn < 16; nn += 8) {
                const float4 v = *reinterpret_cast<const float4*>(
                    &g_w2t[((pu + 1) * 16 + nn) * 128 + k4]);
                *reinterpret_cast<float4*>(&Wn[nn * W2_STR + k4]) = v;
            }
        }

#pragma unroll
        for (int h = 0; h < 2; h++) {
            float d0 = 0.f, d1 = 0.f, d2 = 0.f, d3 = 0.f;
            const float* Bb = Wb + (h * 8 + g) * W2_STR + q;
#pragma unroll
            for (int ks = 0; ks < 16; ks++) {
                const uint32_t b0 = fbits(Bb[ks * 8]);
                const uint32_t b1 = fbits(Bb[ks * 8 + 4]);
                mma_tf32(d0, d1, d2, d3, Af[ks][0], Af[ks][1], Af[ks][2], Af[ks][3], b0, b1);
            }
            if (pu < 32) {
                const float s0 = Ss[r0 * 33 + pu];
                const float s8 = Ss[(r0 + 8) * 33 + pu];
                fs[h][0] = fmaf(s0, d0, fs[h][0]);
                fs[h][1] = fmaf(s0, d1, fs[h][1]);
                fs[h][2] = fmaf(s8, d2, fs[h][2]);
                fs[h][3] = fmaf(s8, d3, fs[h][3]);
            } else {
                const int qq = pu - 32;
                const int off = (qq >> 4) * 48 + (qq & 15) * 3;
                if (er0 < E) {
                    const float* vp = &g_V[er0 * 144 + off];
#pragma unroll
                    for (int i = 0; i < 3; i++) {
                        fva[h][0][i] = fmaf(d0, vp[i], fva[h][0][i]);
                        fva[h][1][i] = fmaf(d1, vp[i], fva[h][1][i]);
                    }
                }
                if (er8 < E) {
                    const float* vp = &g_V[er8 * 144 + off];
#pragma unroll
                    for (int i = 0; i < 3; i++) {
                        fva[h][2][i] = fmaf(d2, vp[i], fva[h][2][i]);
                        fva[h][3][i] = fmaf(d3, vp[i], fva[h][3][i]);
                    }
                }
            }
        }
        __syncthreads();
    }

    // ---- writeout: thread owns (er0, er8) x (v0, v0+1) per h ----
    const int c_lo = 2 * q;
#pragma unroll
    for (int h = 0; h < 2; h++) {
        const int v0 = h * 8 + c_lo;
        if (er0 < E) {
            g_fs[er0 * 16 + v0]     = C_FS * fs[h][0];
            g_fs[er0 * 16 + v0 + 1] = C_FS * fs[h][1];
#pragma unroll
            for (int i = 0; i < 3; i++) {
                g_fv[er0 * 48 + v0 * 3 + i]       = C_FV * fva[h][0][i];
                g_fv[er0 * 48 + (v0 + 1) * 3 + i] = C_FV * fva[h][1][i];
            }
        }
        if (er8 < E) {
            g_fs[er8 * 16 + v0]     = C_FS * fs[h][2];
            g_fs[er8 * 16 + v0 + 1] = C_FS * fs[h][3];
#pragma unroll
            for (int i = 0; i < 3; i++) {
                g_fv[er8 * 48 + v0 * 3 + i]       = C_FV * fva[h][2][i];
                g_fv[er8 * 48 + (v0 + 1) * 3 + i] = C_FV * fva[h][3][i];
            }
        }
    }
}

// ---------------- final output ----------------
__global__ void k_out(float* __restrict__ out, int E) {
    const int idx = blockIdx.x * blockDim.x + threadIdx.x;
    if (idx >= E * 3) return;
    const int e = idx / 3, i = idx - e * 3;
    float acc = 0.f;
#pragma unroll
    for (int u = 0; u < 16; u++)
        acc = fmaf(g_wenv1[e * 16 + u], g_fv[e * 48 + u * 3 + i], acc);
    out[idx] = INV_SM * acc;
}

// ---------------- host driver ----------------
extern "C" void kernel_launch(void* const* d_in, const int* in_sizes, int n_in,
                              void* d_out, int out_size) {
    const float* edge_attr  = (const float*)d_in[0];
    const float* node_attrs = (const float*)d_in[1];
    const float* edge_embed = (const float*)d_in[2];
    const float* edge_u     = (const float*)d_in[3];
    const int*   edge_index = (const int*)d_in[4];
    const float* w2b1    = (const float*)d_in[5];
    const float* w2b2    = (const float*)d_in[6];
    const float* lat1_w1 = (const float*)d_in[7];
    const float* lat1_w2 = (const float*)d_in[8];
    const float* env0_w1 = (const float*)d_in[9];
    const float* env0_w2 = (const float*)d_in[10];
    const float* env1_w1 = (const float*)d_in[11];
    const float* env1_w2 = (const float*)d_in[12];
    const float* l2w0_w1 = (const float*)d_in[13];
    const float* l2w0_w2 = (const float*)d_in[14];
    const float* l2w1_w1 = (const float*)d_in[15];
    const float* l2w1_w2 = (const float*)d_in[16];
    const float* envlin_ws = (const float*)d_in[17];
    const float* envlin_wv = (const float*)d_in[18];
    const float* fl2w_w1 = (const float*)d_in[19];
    const float* fl2w_w2 = (const float*)d_in[20];
    float* out = (float*)d_out;

    const int E = in_sizes[0] / 4;
    const int N = in_sizes[1] / 4;
    if (E > MAX_E || N > MAX_N) return;

    float *p_lat, *p_scal, *p_w0, *p_wenv1, *p_env_s, *p_env_v, *p_w1t, *p_w2t;
    cudaGetSymbolAddress((void**)&p_lat, g_lat);
    cudaGetSymbolAddress((void**)&p_scal, g_scal);
    cudaGetSymbolAddress((void**)&p_w0, g_w0);
    cudaGetSymbolAddress((void**)&p_wenv1, g_wenv1);
    cudaGetSymbolAddress((void**)&p_env_s, g_env_s);
    cudaGetSymbolAddress((void**)&p_env_v, g_env_v);
    cudaGetSymbolAddress((void**)&p_w1t, g_w1t);
    cudaGetSymbolAddress((void**)&p_w2t, g_w2t);

    const size_t smA = (64 * 16 + 64 * 128) * sizeof(float);
    const size_t smB = (64 * 128 + 64 * 128) * sizeof(float);
    const size_t smC = (64 * 160 + 64 * 128) * sizeof(float);

    cudaFuncSetAttribute((const void*)k_first, cudaFuncAttributeMaxDynamicSharedMemorySize, (int)smA);
    cudaFuncSetAttribute((const void*)k_mlp<128,128,64,0>,  cudaFuncAttributeMaxDynamicSharedMemorySize, (int)smB);
    cudaFuncSetAttribute((const void*)k_mlp<128,128,32,0>,  cudaFuncAttributeMaxDynamicSharedMemorySize, (int)smB);
    cudaFuncSetAttribute((const void*)k_mlp<160,128,128,1>, cudaFuncAttributeMaxDynamicSharedMemorySize, (int)smC);
    cudaFuncSetAttribute((const void*)k_mlp<160,128,16,0>,  cudaFuncAttributeMaxDynamicSharedMemorySize, (int)smC);
    cudaFuncSetAttribute((const void*)k_l2w_ts, cudaFuncAttributeMaxDynamicSharedMemorySize, L2W_SMEM);

    const int nb    = (E + 63) / 64;
    const int nb128 = (E + 127) / 128;
    const int nb16  = (E * 16 + 255) / 256;

    // stage 0
    k_first<<<nb, 256, smA>>>(node_attrs, edge_embed, edge_u, edge_index, w2b1, w2b2, E);
    k_mlp<128,128,64,0><<<nb, 256, smB>>>(p_lat, p_lat, env0_w1, env0_w2, p_w0, E);
    k_weighter<<<nb16, 256>>>(edge_attr, E);

    // ---- layer 0 ----
    cudaMemsetAsync(p_env_s, 0, (size_t)N * 16 * sizeof(float));
    cudaMemsetAsync(p_env_v, 0, (size_t)N * 48 * sizeof(float));
    k_scatter<<<nb16, 256>>>(p_w0, 64, 32, edge_attr, edge_index, E);
    k_envlin<<<(N * 16 + 255) / 256, 256>>>(envlin_ws, envlin_wv, N);
    k_combine<<<nb16, 256>>>(edge_index, E);
    k_transpose<<<(160 * 128 + 255) / 256, 256>>>(l2w0_w1, p_w1t, 160, 128);
    k_transpose<<<(128 * 1280 + 255) / 256, 256>>>(l2w0_w2, p_w2t, 128, 1280);
    k_l2w_ts<<<nb128, 256, L2W_SMEM>>>(E);

    // ---- layer 1 ----
    k_mlp<160,128,128,1><<<nb, 256, smC>>>(p_lat, p_scal, lat1_w1, lat1_w2, p_lat, E);
    k_mlp<128,128,32,0><<<nb, 256, smB>>>(p_lat, p_lat, env1_w1, env1_w2, p_wenv1, E);
    cudaMemsetAsync(p_env_s, 0, (size_t)N * 16 * sizeof(float));
    cudaMemsetAsync(p_env_v, 0, (size_t)N * 48 * sizeof(float));
    k_scatter<<<nb16, 256>>>(p_wenv1, 32, 0, edge_attr, edge_index, E);
    k_envlin<<<(N * 16 + 255) / 256, 256>>>(envlin_ws + 256, envlin_wv + 256, N);
    k_combine<<<nb16, 256>>>(edge_index, E);
    k_transpose<<<(160 * 128 + 255) / 256, 256>>>(l2w1_w1, p_w1t, 160, 128);
    k_transpose<<<(128 * 1280 + 255) / 256, 256>>>(l2w1_w2, p_w2t, 128, 1280);
    k_l2w_ts<<<nb128, 256, L2W_SMEM>>>(E);

    // ---- final ----
    k_mlp<160,128,16,0><<<nb, 256, smC>>>(p_lat, p_scal, fl2w_w1, fl2w_w2, p_wenv1, E);
    k_out<<<(E * 3 + 255) / 256, 256>>>(out, E);
}

// round 5
// speedup vs baseline: 2.1549x; 1.2555x over previous
#include <cuda_runtime.h>
#include <cstdint>

// ---------------- problem constants ----------------
#define MAX_E 120000
#define MAX_N 5000

typedef unsigned long long u64;

// ---------------- scratch (static __device__, allocation-free) ----------------
__device__ float g_cut[MAX_E];
__device__ float g_lat[MAX_E * 128];
__device__ float g_w0[MAX_E * 64];
__device__ float g_wenv1[MAX_E * 32];
__device__ float g_fs[MAX_E * 16];
__device__ float g_fv[MAX_E * 48];
__device__ float g_scal[MAX_E * 32];
__device__ float g_V[MAX_E * 144];
__device__ float g_env_s[MAX_N * 16];
__device__ float g_env_v[MAX_N * 48];
__device__ float g_env_s2[MAX_N * 16];
__device__ float g_env_v2[MAX_N * 48];
__device__ float g_w1f[16 * 20 * 64];    // W1 frag-packed: [ch*20+ks][lane*2+z]
__device__ float g_w2f[80 * 2 * 16 * 64];// W2 frag-packed: [((pu*2+h)*16+ks)][lane*2+z]

// ---------------- math constants ----------------
constexpr float C_OLD    = 0.8944271909999159f;
constexpr float A_C_OLD  = 0.4472135954999579f;
constexpr float INV_S3   = 0.5773502691896258f;
constexpr float INV_S2   = 0.7071067811865476f;
constexpr float C_FS     = 0.17677669529663687f;
constexpr float C_FV     = 0.14433756729740643f;
constexpr float NORM_LIN = 0.05590169943749474f;
constexpr float INV_SM   = 0.25f;

__device__ __forceinline__ float silu_f(float x) { return x / (1.f + __expf(-x)); }

// ---------------- packed f32x2 helpers ----------------
__device__ __forceinline__ u64 pack2(float lo, float hi) {
    u64 r;
    asm("mov.b64 %0, {%1, %2};" : "=l"(r) : "f"(lo), "f"(hi));
    return r;
}
__device__ __forceinline__ void unpack2(u64 v, float& lo, float& hi) {
    asm("mov.b64 {%0, %1}, %2;" : "=f"(lo), "=f"(hi) : "l"(v));
}
__device__ __forceinline__ void ffma2(u64& d, u64 a, u64 b) {
    asm("fma.rn.f32x2 %0, %1, %2, %0;" : "+l"(d) : "l"(a), "l"(b));
}

// ---------------- tf32 helpers ----------------
__device__ __forceinline__ float tf32r(float x) {
    uint32_t u;
    asm("cvt.rna.tf32.f32 %0, %1;" : "=r"(u) : "f"(x));
    return __uint_as_float(u);
}
__device__ __forceinline__ void mma_tf32(float& d0, float& d1, float& d2, float& d3,
                                         uint32_t a0, uint32_t a1, uint32_t a2, uint32_t a3,
                                         uint32_t b0, uint32_t b1) {
    asm volatile(
        "mma.sync.aligned.m16n8k8.row.col.f32.tf32.tf32.f32 "
        "{%0,%1,%2,%3}, {%4,%5,%6,%7}, {%8,%9}, {%0,%1,%2,%3};"
        : "+f"(d0), "+f"(d1), "+f"(d2), "+f"(d3)
        : "r"(a0), "r"(a1), "r"(a2), "r"(a3), "r"(b0), "r"(b1));
}
__device__ __forceinline__ uint32_t fbits(float x) { return __float_as_uint(x); }

// ---------------- scalar GEMM building blocks (proven) ----------------
template <int IN>
__device__ __forceinline__ void gemm1_silu(const float* Xs, const float* __restrict__ W1,
                                           float* Hs, int t) {
    const int eg = t >> 4;
    const int hg = t & 15;
    u64 acc[4][4];
#pragma unroll
    for (int i = 0; i < 4; i++)
#pragma unroll
        for (int j = 0; j < 4; j++) acc[i][j] = 0ULL;
#pragma unroll 4
    for (int k = 0; k < IN; k++) {
        const float4 wa = *reinterpret_cast<const float4*>(W1 + k * 128 + hg * 8);
        const float4 wb = *reinterpret_cast<const float4*>(W1 + k * 128 + hg * 8 + 4);
        const u64 w0 = pack2(wa.x, wa.y), w1 = pack2(wa.z, wa.w);
        const u64 w2 = pack2(wb.x, wb.y), w3 = pack2(wb.z, wb.w);
#pragma unroll
        for (int i = 0; i < 4; i++) {
            const float x = Xs[(eg * 4 + i) * IN + k];
            const u64 xx = pack2(x, x);
            ffma2(acc[i][0], xx, w0);
            ffma2(acc[i][1], xx, w1);
            ffma2(acc[i][2], xx, w2);
            ffma2(acc[i][3], xx, w3);
        }
    }
#pragma unroll
    for (int i = 0; i < 4; i++)
#pragma unroll
        for (int j = 0; j < 4; j++) {
            float lo, hi;
            unpack2(acc[i][j], lo, hi);
            float* hp = &Hs[(eg * 4 + i) * 128 + hg * 8 + 2 * j];
            hp[0] = silu_f(lo);
            hp[1] = silu_f(hi);
        }
}

template <int IN, int WA>
__device__ __forceinline__ void load_xs(float* Xs, const float* __restrict__ Xa,
                                        const float* __restrict__ Xb, int e0, int E, int t) {
    for (int idx = t; idx < 64 * IN; idx += 256) {
        const int le = idx / IN;
        const int c = idx - le * IN;
        const int e = e0 + le;
        float v = 0.f;
        if (e < E) {
            if (c < WA) v = Xa[e * WA + c];
            else        v = Xb[e * (IN - WA) + (c - WA)];
        }
        Xs[idx] = v;
    }
}

template <int IN, int WA, int OUT, int EPI>
__global__ void __launch_bounds__(256)
k_mlp(const float* __restrict__ Xa, const float* __restrict__ Xb,
      const float* __restrict__ W1, const float* __restrict__ W2,
      float* __restrict__ Y, int E) {
    extern __shared__ float sm[];
    float* Xs = sm;
    float* Hs = sm + 64 * IN;
    const int t = threadIdx.x;
    const int e0 = blockIdx.x * 64;

    load_xs<IN, WA>(Xs, Xa, Xb, e0, E, t);
    __syncthreads();
    gemm1_silu<IN>(Xs, W1, Hs, t);
    __syncthreads();

    constexpr int OPT = (OUT >= 32) ? 8 : 4;
    constexpr int NOG = OUT / OPT;
    constexpr int EPT = (64 * NOG) / 256;
    constexpr int OP2 = OPT / 2;
    const int og = t % NOG;
    const int eg = t / NOG;

    u64 acc[EPT][OP2];
#pragma unroll
    for (int i = 0; i < EPT; i++)
#pragma unroll
        for (int j = 0; j < OP2; j++) acc[i][j] = 0ULL;

#pragma unroll 4
    for (int k = 0; k < 128; k++) {
        const float* wr = W2 + k * OUT + og * OPT;
        u64 w[OP2];
        {
            float4 t0 = *reinterpret_cast<const float4*>(wr);
            w[0] = pack2(t0.x, t0.y);
            w[1] = pack2(t0.z, t0.w);
            if (OPT == 8) {
                float4 t1 = *reinterpret_cast<const float4*>(wr + 4);
                w[2] = pack2(t1.x, t1.y);
                w[3] = pack2(t1.z, t1.w);
            }
        }
#pragma unroll
        for (int i = 0; i < EPT; i++) {
            const float h = Hs[(eg * EPT + i) * 128 + k];
            const u64 hh = pack2(h, h);
#pragma unroll
            for (int j = 0; j < OP2; j++) ffma2(acc[i][j], hh, w[j]);
        }
    }

#pragma unroll
    for (int i = 0; i < EPT; i++) {
        const int e = e0 + eg * EPT + i;
        if (e >= E) continue;
        if (EPI == 0) {
#pragma unroll
            for (int j = 0; j < OP2; j++) {
                float lo, hi;
                unpack2(acc[i][j], lo, hi);
                Y[e * OUT + og * OPT + 2 * j + 0] = lo;
                Y[e * OUT + og * OPT + 2 * j + 1] = hi;
            }
        } else {
            const float ac = A_C_OLD * g_cut[e];
#pragma unroll
            for (int j = 0; j < OP2; j++) {
                float lo, hi;
                unpack2(acc[i][j], lo, hi);
                const int o = og * OPT + 2 * j;
                g_lat[e * 128 + o + 0] = C_OLD * g_lat[e * 128 + o + 0] + ac * lo;
                g_lat[e * 128 + o + 1] = C_OLD * g_lat[e * 128 + o + 1] + ac * hi;
            }
        }
    }
}

// ---------------- first stage ----------------
__global__ void __launch_bounds__(256)
k_first(const float* __restrict__ node_attrs, const float* __restrict__ edge_embed,
        const float* __restrict__ edge_u, const int* __restrict__ edge_index,
        const float* __restrict__ W1, const float* __restrict__ W2, int E) {
    extern __shared__ float sm[];
    float* Xs = sm;
    float* Hs = sm + 64 * 16;
    const int t = threadIdx.x;
    const int e0 = blockIdx.x * 64;

    for (int idx = t; idx < 64 * 16; idx += 256) {
        const int le = idx >> 4, c = idx & 15;
        const int e = e0 + le;
        float v = 0.f;
        if (e < E) {
            if (c < 4)       v = node_attrs[edge_index[e] * 4 + c];
            else if (c < 8)  v = node_attrs[edge_index[E + e] * 4 + (c - 4)];
            else             v = edge_embed[e * 8 + (c - 8)];
        }
        Xs[idx] = v;
    }
    if (t < 64) {
        const int e = e0 + t;
        if (e < E) {
            const float u = edge_u[e];
            const float u2 = u * u, u3 = u2 * u, u6 = u3 * u3;
            const float f = 1.f - 28.f * u6 + 48.f * u6 * u - 21.f * u6 * u2;
            g_cut[e] = (u < 1.f) ? f : 0.f;
        }
    }
    __syncthreads();
    gemm1_silu<16>(Xs, W1, Hs, t);
    __syncthreads();

    const int eg = t >> 4, og = t & 15;
    u64 acc[4][4];
#pragma unroll
    for (int i = 0; i < 4; i++)
#pragma unroll
        for (int j = 0; j < 4; j++) acc[i][j] = 0ULL;
#pragma unroll 4
    for (int k = 0; k < 128; k++) {
        const float4 wa = *reinterpret_cast<const float4*>(W2 + k * 128 + og * 8);
        const float4 wb = *reinterpret_cast<const float4*>(W2 + k * 128 + og * 8 + 4);
        const u64 w0 = pack2(wa.x, wa.y), w1 = pack2(wa.z, wa.w);
        const u64 w2 = pack2(wb.x, wb.y), w3 = pack2(wb.z, wb.w);
#pragma unroll
        for (int i = 0; i < 4; i++) {
            const float h = Hs[(eg * 4 + i) * 128 + k];
            const u64 hh = pack2(h, h);
            ffma2(acc[i][0], hh, w0);
            ffma2(acc[i][1], hh, w1);
            ffma2(acc[i][2], hh, w2);
            ffma2(acc[i][3], hh, w3);
        }
    }
#pragma unroll
    for (int i = 0; i < 4; i++) {
        const int e = e0 + eg * 4 + i;
        if (e >= E) continue;
        const float cc = g_cut[e];
#pragma unroll
        for (int j = 0; j < 4; j++) {
            float lo, hi;
            unpack2(acc[i][j], lo, hi);
            g_lat[e * 128 + og * 8 + 2 * j + 0] = cc * lo;
            g_lat[e * 128 + og * 8 + 2 * j + 1] = cc * hi;
        }
    }
}

// ---------------- small per-edge / per-node kernels ----------------
__global__ void k_weighter(const float* __restrict__ edge_attr, int E) {
    const int idx = blockIdx.x * blockDim.x + threadIdx.x;
    if (idx >= E * 16) return;
    const int e = idx >> 4, u = idx & 15;
    const float ws = g_w0[e * 64 + 2 * u];
    const float wv = g_w0[e * 64 + 2 * u + 1];
    g_fs[e * 16 + u] = ws * edge_attr[e * 4 + 0];
    g_fv[e * 48 + u * 3 + 0] = wv * edge_attr[e * 4 + 1];
    g_fv[e * 48 + u * 3 + 1] = wv * edge_attr[e * 4 + 2];
    g_fv[e * 48 + u * 3 + 2] = wv * edge_attr[e * 4 + 3];
}

__global__ void k_scatter(const float* __restrict__ wenv, int stride, int off,
                          const float* __restrict__ edge_attr,
                          const int* __restrict__ edge_index, int E) {
    const int idx = blockIdx.x * blockDim.x + threadIdx.x;
    if (idx >= E * 16) return;
    const int e = idx >> 4, u = idx & 15;
    const int c = edge_index[e];
    const float ws = wenv[e * stride + off + 2 * u];
    const float wv = wenv[e * stride + off + 2 * u + 1];
    atomicAdd(&g_env_s[c * 16 + u], ws * edge_attr[e * 4 + 0]);
    atomicAdd(&g_env_v[c * 48 + u * 3 + 0], wv * edge_attr[e * 4 + 1]);
    atomicAdd(&g_env_v[c * 48 + u * 3 + 1], wv * edge_attr[e * 4 + 2]);
    atomicAdd(&g_env_v[c * 48 + u * 3 + 2], wv * edge_attr[e * 4 + 3]);
}

__global__ void k_envlin(const float* __restrict__ Ws, const float* __restrict__ Wv, int N) {
    const int idx = blockIdx.x * blockDim.x + threadIdx.x;
    if (idx >= N * 16) return;
    const int n = idx >> 4, v = idx & 15;
    float s = 0.f, v0 = 0.f, v1 = 0.f, v2 = 0.f;
#pragma unroll
    for (int u = 0; u < 16; u++) {
        const float wsv = Ws[u * 16 + v];
        const float wvv = Wv[u * 16 + v];
        s  = fmaf(g_env_s[n * 16 + u], wsv, s);
        v0 = fmaf(g_env_v[n * 48 + u * 3 + 0], wvv, v0);
        v1 = fmaf(g_env_v[n * 48 + u * 3 + 1], wvv, v1);
        v2 = fmaf(g_env_v[n * 48 + u * 3 + 2], wvv, v2);
    }
    g_env_s2[n * 16 + v] = s * NORM_LIN;
    g_env_v2[n * 48 + v * 3 + 0] = v0 * NORM_LIN;
    g_env_v2[n * 48 + v * 3 + 1] = v1 * NORM_LIN;
    g_env_v2[n * 48 + v * 3 + 2] = v2 * NORM_LIN;
}

__global__ void k_combine(const int* __restrict__ edge_index, int E) {
    const int idx = blockIdx.x * blockDim.x + threadIdx.x;
    if (idx >= E * 16) return;
    const int e = idx >> 4, u = idx & 15;
    const int c = edge_index[e];
    const float es  = g_env_s2[c * 16 + u];
    const float ev0 = g_env_v2[c * 48 + u * 3 + 0];
    const float ev1 = g_env_v2[c * 48 + u * 3 + 1];
    const float ev2 = g_env_v2[c * 48 + u * 3 + 2];
    const float fsv = g_fs[e * 16 + u];
    const float fv0 = g_fv[e * 48 + u * 3 + 0];
    const float fv1 = g_fv[e * 48 + u * 3 + 1];
    const float fv2 = g_fv[e * 48 + u * 3 + 2];

    g_scal[e * 32 + 2 * u]     = fsv * es;
    g_scal[e * 32 + 2 * u + 1] = (fv0 * ev0 + fv1 * ev1 + fv2 * ev2) * INV_S3;

    float* Vp = &g_V[e * 144];
    Vp[u * 3 + 0] = fsv * ev0;
    Vp[u * 3 + 1] = fsv * ev1;
    Vp[u * 3 + 2] = fsv * ev2;
    Vp[48 + u * 3 + 0] = fv0 * es;
    Vp[48 + u * 3 + 1] = fv1 * es;
    Vp[48 + u * 3 + 2] = fv2 * es;
    Vp[96 + u * 3 + 0] = (fv1 * ev2 - fv2 * ev1) * INV_S2;
    Vp[96 + u * 3 + 1] = (fv2 * ev0 - fv0 * ev2) * INV_S2;
    Vp[96 + u * 3 + 2] = (fv0 * ev1 - fv1 * ev0) * INV_S2;
}

// ---------------- weight frag-packing (tf32-rounded, coalesced B-frags) ----------------
// g_w1f[(ch*20+ks)*64 + lane*2 + z] = W1[k][n], n=ch*8+(lane>>2), k=ks*8+(lane&3)+z*4
__global__ void k_pack_w1(const float* __restrict__ W1) {
    const int idx = blockIdx.x * blockDim.x + threadIdx.x;
    if (idx >= 16 * 20 * 64) return;
    const int frag = idx >> 6;
    const int r = idx & 63;
    const int lane = r >> 1, z = r & 1;
    const int ch = frag / 20, ks = frag % 20;
    const int n = ch * 8 + (lane >> 2);
    const int k = ks * 8 + (lane & 3) + z * 4;
    g_w1f[idx] = tf32r(W1[k * 128 + n]);
}
// g_w2f[((pu*2+h)*16+ks)*64 + lane*2 + z] = W2[k][n], n=pu*16+h*8+(lane>>2), k=ks*8+(lane&3)+z*4
__global__ void k_pack_w2(const float* __restrict__ W2) {
    const int idx = blockIdx.x * blockDim.x + threadIdx.x;
    if (idx >= 80 * 2 * 16 * 64) return;
    const int frag = idx >> 6;
    const int r = idx & 63;
    const int lane = r >> 1, z = r & 1;
    const int puh = frag >> 4, ks = frag & 15;
    const int pu = puh >> 1, h = puh & 1;
    const int n = pu * 16 + h * 8 + (lane >> 2);
    const int k = ks * 8 + (lane & 3) + z * 4;
    g_w2f[idx] = tf32r(W2[k * 1280 + n]);
}

// ---------------- mma.sync tf32 fused l2w (v2) ----------------
// 256 edges/CTA, 8 warps x 32 rows (2 m-tiles). A-frags in regs; B-frags are
// coalesced LDG.64 from frag-packed weights. H bounced per-warp through smem.
// V staged in 8-pu smem blocks. No per-pu syncthreads. lw never materialized.
#define H_STR  132
#define SM_SS  (256 * H_STR)
#define SM_VS  (SM_SS + 256 * 33)
#define L2W_SMEM_B ((SM_VS + 256 * 25) * 4)   // 194560 bytes

__device__ __forceinline__ float l2w_xval(int e, int k, int E) {
    if (e >= E) return 0.f;
    const float v = (k < 128) ? g_lat[e * 128 + k] : g_scal[e * 32 + (k - 128)];
    return tf32r(v);
}

__global__ void __launch_bounds__(256, 1)
k_l2w_ts(int E) {
    extern __shared__ float sm[];
    float* Hs = sm;
    float* Ss = sm + SM_SS;
    float* Vs = sm + SM_VS;
    const int t = threadIdx.x, lane = t & 31, w = t >> 5;
    const int g = lane >> 2, q = lane & 3;
    const int e0 = blockIdx.x * 256;
    const int rb = w * 32;          // warp row base; thread rows rb+g+8*rg, rg=0..3

    // stage Ss[el][pu]
    for (int idx = t; idx < 256 * 32; idx += 256) {
        const int el = idx >> 5, pu = idx & 31;
        const int e = e0 + el;
        Ss[el * 33 + pu] = (e < E) ? g_scal[e * 32 + 2 * (pu & 15) + (pu >> 4)] : 0.f;
    }
    __syncthreads();

    // ---- GEMM1: acc[ch 16][2m*4] over K=160 ----
    {
        float acc[16][8];
#pragma unroll
        for (int c = 0; c < 16; c++)
#pragma unroll
            for (int j = 0; j < 8; j++) acc[c][j] = 0.f;

#pragma unroll 1
        for (int ks = 0; ks < 20; ks++) {
            const int k0 = ks * 8;
            uint32_t a[2][4];
#pragma unroll
            for (int m = 0; m < 2; m++) {
                const int er0 = e0 + rb + 16 * m + g;
                a[m][0] = fbits(l2w_xval(er0,     k0 + q,     E));
                a[m][1] = fbits(l2w_xval(er0 + 8, k0 + q,     E));
                a[m][2] = fbits(l2w_xval(er0,     k0 + q + 4, E));
                a[m][3] = fbits(l2w_xval(er0 + 8, k0 + q + 4, E));
            }
#pragma unroll
            for (int ch = 0; ch < 16; ch++) {
                const float2 b = *reinterpret_cast<const float2*>(
                    &g_w1f[(ch * 20 + ks) * 64 + lane * 2]);
                mma_tf32(acc[ch][0], acc[ch][1], acc[ch][2], acc[ch][3],
                         a[0][0], a[0][1], a[0][2], a[0][3], fbits(b.x), fbits(b.y));
                mma_tf32(acc[ch][4], acc[ch][5], acc[ch][6], acc[ch][7],
                         a[1][0], a[1][1], a[1][2], a[1][3], fbits(b.x), fbits(b.y));
            }
        }
        // silu -> Hs (tf32). acc[ch][4m+2s+c] -> row rb+16m+8s+g, col ch*8+2q+c
#pragma unroll
        for (int ch = 0; ch < 16; ch++) {
#pragma unroll
            for (int m = 0; m < 2; m++)
#pragma unroll
                for (int s = 0; s < 2; s++) {
                    const int row = rb + 16 * m + 8 * s + g;
                    const int col = ch * 8 + 2 * q;
                    Hs[row * H_STR + col]     = tf32r(silu_f(acc[ch][4 * m + 2 * s + 0]));
                    Hs[row * H_STR + col + 1] = tf32r(silu_f(acc[ch][4 * m + 2 * s + 1]));
                }
        }
        __syncwarp();
    }

    // ---- load A-frags of GEMM2 (H) into regs ----
    uint32_t Af[16][2][4];
#pragma unroll
    for (int ks = 0; ks < 16; ks++) {
        const int k0 = ks * 8;
#pragma unroll
        for (int m = 0; m < 2; m++) {
            const int r0 = rb + 16 * m + g;
            Af[ks][m][0] = fbits(Hs[r0 * H_STR + k0 + q]);
            Af[ks][m][1] = fbits(Hs[(r0 + 8) * H_STR + k0 + q]);
            Af[ks][m][2] = fbits(Hs[r0 * H_STR + k0 + q + 4]);
            Af[ks][m][3] = fbits(Hs[(r0 + 8) * H_STR + k0 + q + 4]);
        }
    }

    // ---- GEMM2 + contraction: 10 blocks of 8 pu ----
    float fs[4][2][2];          // [rg][h][c]
    float fv[4][2][2][3];       // [rg][h][c][i]
#pragma unroll
    for (int rg = 0; rg < 4; rg++)
#pragma unroll
        for (int h = 0; h < 2; h++)
#pragma unroll
            for (int c = 0; c < 2; c++) {
                fs[rg][h][c] = 0.f;
                fv[rg][h][c][0] = 0.f; fv[rg][h][c][1] = 0.f; fv[rg][h][c][2] = 0.f;
            }

#pragma unroll 1
    for (int blk = 0; blk < 10; blk++) {
        if (blk >= 4) {
            __syncthreads();
            const int pb3 = (blk - 4) * 24;   // (pu-32)*3 base into g_V row
            for (int idx = t; idx < 256 * 24; idx += 256) {
                const int el = idx / 24, c = idx - el * 24;
                const int e = e0 + el;
                Vs[el * 25 + c] = (e < E) ? g_V[e * 144 + pb3 + c] : 0.f;
            }
            __syncthreads();
        }
#pragma unroll 1
        for (int j = 0; j < 8; j++) {
            const int pu = blk * 8 + j;
#pragma unroll
            for (int h = 0; h < 2; h++) {
                float d[8];
#pragma unroll
                for (int x = 0; x < 8; x++) d[x] = 0.f;
                const int fb = ((pu * 2 + h) * 16) * 64;
#pragma unroll
                for (int ks = 0; ks < 16; ks++) {
                    const float2 b = *reinterpret_cast<const float2*>(
                        &g_w2f[fb + ks * 64 + lane * 2]);
                    mma_tf32(d[0], d[1], d[2], d[3],
                             Af[ks][0][0], Af[ks][0][1], Af[ks][0][2], Af[ks][0][3],
                             fbits(b.x), fbits(b.y));
                    mma_tf32(d[4], d[5], d[6], d[7],
                             Af[ks][1][0], Af[ks][1][1], Af[ks][1][2], Af[ks][1][3],
                             fbits(b.x), fbits(b.y));
                }
                if (blk < 4) {
#pragma unroll
                    for (int rg = 0; rg < 4; rg++) {
                        const float s = Ss[(rb + rg * 8 + g) * 33 + pu];
                        fs[rg][h][0] = fmaf(s, d[2 * rg + 0], fs[rg][h][0]);
                        fs[rg][h][1] = fmaf(s, d[2 * rg + 1], fs[rg][h][1]);
                    }
                } else {
#pragma unroll
                    for (int rg = 0; rg < 4; rg++) {
                        const int base = (rb + rg * 8 + g) * 25 + j * 3;
                        const float v0 = Vs[base], v1 = Vs[base + 1], v2 = Vs[base + 2];
#pragma unroll
                        for (int c = 0; c < 2; c++) {
                            const float dd = d[2 * rg + c];
                            fv[rg][h][c][0] = fmaf(dd, v0, fv[rg][h][c][0]);
                            fv[rg][h][c][1] = fmaf(dd, v1, fv[rg][h][c][1]);
                            fv[rg][h][c][2] = fmaf(dd, v2, fv[rg][h][c][2]);
                        }
                    }
                }
            }
        }
    }

    // ---- writeout ----
#pragma unroll
    for (int rg = 0; rg < 4; rg++) {
        const int e = e0 + rb + rg * 8 + g;
        if (e >= E) continue;
#pragma unroll
        for (int h = 0; h < 2; h++)
#pragma unroll
            for (int c = 0; c < 2; c++) {
                const int v = h * 8 + 2 * q + c;
                g_fs[e * 16 + v] = C_FS * fs[rg][h][c];
                g_fv[e * 48 + v * 3 + 0] = C_FV * fv[rg][h][c][0];
                g_fv[e * 48 + v * 3 + 1] = C_FV * fv[rg][h][c][1];
                g_fv[e * 48 + v * 3 + 2] = C_FV * fv[rg][h][c][2];
            }
    }
}

// ---------------- final output ----------------
__global__ void k_out(float* __restrict__ out, int E) {
    const int idx = blockIdx.x * blockDim.x + threadIdx.x;
    if (idx >= E * 3) return;
    const int e = idx / 3, i = idx - e * 3;
    float acc = 0.f;
#pragma unroll
    for (int u = 0; u < 16; u++)
        acc = fmaf(g_wenv1[e * 16 + u], g_fv[e * 48 + u * 3 + i], acc);
    out[idx] = INV_SM * acc;
}

// ---------------- host driver ----------------
extern "C" void kernel_launch(void* const* d_in, const int* in_sizes, int n_in,
                              void* d_out, int out_size) {
    const float* edge_attr  = (const float*)d_in[0];
    const float* node_attrs = (const float*)d_in[1];
    const float* edge_embed = (const float*)d_in[2];
    const float* edge_u     = (const float*)d_in[3];
    const int*   edge_index = (const int*)d_in[4];
    const float* w2b1    = (const float*)d_in[5];
    const float* w2b2    = (const float*)d_in[6];
    const float* lat1_w1 = (const float*)d_in[7];
    const float* lat1_w2 = (const float*)d_in[8];
    const float* env0_w1 = (const float*)d_in[9];
    const float* env0_w2 = (const float*)d_in[10];
    const float* env1_w1 = (const float*)d_in[11];
    const float* env1_w2 = (const float*)d_in[12];
    const float* l2w0_w1 = (const float*)d_in[13];
    const float* l2w0_w2 = (const float*)d_in[14];
    const float* l2w1_w1 = (const float*)d_in[15];
    const float* l2w1_w2 = (const float*)d_in[16];
    const float* envlin_ws = (const float*)d_in[17];
    const float* envlin_wv = (const float*)d_in[18];
    const float* fl2w_w1 = (const float*)d_in[19];
    const float* fl2w_w2 = (const float*)d_in[20];
    float* out = (float*)d_out;

    const int E = in_sizes[0] / 4;
    const int N = in_sizes[1] / 4;
    if (E > MAX_E || N > MAX_N) return;

    float *p_lat, *p_scal, *p_w0, *p_wenv1, *p_env_s, *p_env_v;
    cudaGetSymbolAddress((void**)&p_lat, g_lat);
    cudaGetSymbolAddress((void**)&p_scal, g_scal);
    cudaGetSymbolAddress((void**)&p_w0, g_w0);
    cudaGetSymbolAddress((void**)&p_wenv1, g_wenv1);
    cudaGetSymbolAddress((void**)&p_env_s, g_env_s);
    cudaGetSymbolAddress((void**)&p_env_v, g_env_v);

    const size_t smA = (64 * 16 + 64 * 128) * sizeof(float);
    const size_t smB = (64 * 128 + 64 * 128) * sizeof(float);
    const size_t smC = (64 * 160 + 64 * 128) * sizeof(float);

    cudaFuncSetAttribute((const void*)k_first, cudaFuncAttributeMaxDynamicSharedMemorySize, (int)smA);
    cudaFuncSetAttribute((const void*)k_mlp<128,128,64,0>,  cudaFuncAttributeMaxDynamicSharedMemorySize, (int)smB);
    cudaFuncSetAttribute((const void*)k_mlp<128,128,32,0>,  cudaFuncAttributeMaxDynamicSharedMemorySize, (int)smB);
    cudaFuncSetAttribute((const void*)k_mlp<160,128,128,1>, cudaFuncAttributeMaxDynamicSharedMemorySize, (int)smC);
    cudaFuncSetAttribute((const void*)k_mlp<160,128,16,0>,  cudaFuncAttributeMaxDynamicSharedMemorySize, (int)smC);
    cudaFuncSetAttribute((const void*)k_l2w_ts, cudaFuncAttributeMaxDynamicSharedMemorySize, L2W_SMEM_B);

    const int nb    = (E + 63) / 64;
    const int nb256 = (E + 255) / 256;
    const int nb16  = (E * 16 + 255) / 256;

    // stage 0
    k_first<<<nb, 256, smA>>>(node_attrs, edge_embed, edge_u, edge_index, w2b1, w2b2, E);
    k_mlp<128,128,64,0><<<nb, 256, smB>>>(p_lat, p_lat, env0_w1, env0_w2, p_w0, E);
    k_weighter<<<nb16, 256>>>(edge_attr, E);

    // ---- layer 0 ----
    cudaMemsetAsync(p_env_s, 0, (size_t)N * 16 * sizeof(float));
    cudaMemsetAsync(p_env_v, 0, (size_t)N * 48 * sizeof(float));
    k_scatter<<<nb16, 256>>>(p_w0, 64, 32, edge_attr, edge_index, E);
    k_envlin<<<(N * 16 + 255) / 256, 256>>>(envlin_ws, envlin_wv, N);
    k_combine<<<nb16, 256>>>(edge_index, E);
    k_pack_w1<<<(16 * 20 * 64 + 255) / 256, 256>>>(l2w0_w1);
    k_pack_w2<<<(80 * 2 * 16 * 64 + 255) / 256, 256>>>(l2w0_w2);
    k_l2w_ts<<<nb256, 256, L2W_SMEM_B>>>(E);

    // ---- layer 1 ----
    k_mlp<160,128,128,1><<<nb, 256, smC>>>(p_lat, p_scal, lat1_w1, lat1_w2, p_lat, E);
    k_mlp<128,128,32,0><<<nb, 256, smB>>>(p_lat, p_lat, env1_w1, env1_w2, p_wenv1, E);
    cudaMemsetAsync(p_env_s, 0, (size_t)N * 16 * sizeof(float));
    cudaMemsetAsync(p_env_v, 0, (size_t)N * 48 * sizeof(float));
    k_scatter<<<nb16, 256>>>(p_wenv1, 32, 0, edge_attr, edge_index, E);
    k_envlin<<<(N * 16 + 255) / 256, 256>>>(envlin_ws + 256, envlin_wv + 256, N);
    k_combine<<<nb16, 256>>>(edge_index, E);
    k_pack_w1<<<(16 * 20 * 64 + 255) / 256, 256>>>(l2w1_w1);
    k_pack_w2<<<(80 * 2 * 16 * 64 + 255) / 256, 256>>>(l2w1_w2);
    k_l2w_ts<<<nb256, 256, L2W_SMEM_B>>>(E);

    // ---- final ----
    k_mlp<160,128,16,0><<<nb, 256, smC>>>(p_lat, p_scal, fl2w_w1, fl2w_w2, p_wenv1, E);
    k_out<<<(E * 3 + 255) / 256, 256>>>(out, E);
}

// round 6
// speedup vs baseline: 2.3548x; 1.0928x over previous
#include <cuda_runtime.h>
#include <cstdint>

// ---------------- problem constants ----------------
#define MAX_E 120000
#define MAX_N 5000

typedef unsigned long long u64;

// ---------------- scratch (static __device__, allocation-free) ----------------
__device__ float g_cut[MAX_E];
__device__ float g_lat[MAX_E * 128];
__device__ float g_w0[MAX_E * 64];
__device__ float g_wenv1[MAX_E * 32];
__device__ float g_fs[MAX_E * 16];
__device__ float g_fv[MAX_E * 48];
__device__ float g_scal[MAX_E * 32];
__device__ float g_V[MAX_E * 144];
__device__ float g_env_s[MAX_N * 16];
__device__ float g_env_v[MAX_N * 48];
__device__ float g_env_s2[MAX_N * 16];
__device__ float g_env_v2[MAX_N * 48];
__device__ float g_w1f[16 * 20 * 64];      // l2w W1 frag-packed (plain tf32)
__device__ float g_w2f[80 * 2 * 16 * 64];  // l2w W2 frag-packed (plain tf32)
__device__ float g_mw1f[16 * 20 * 128];    // MLP W1 frag-packed hi/lo
__device__ float g_mw2f[16 * 16 * 128];    // MLP W2 frag-packed hi/lo

// ---------------- math constants ----------------
constexpr float C_OLD    = 0.8944271909999159f;
constexpr float A_C_OLD  = 0.4472135954999579f;
constexpr float INV_S3   = 0.5773502691896258f;
constexpr float INV_S2   = 0.7071067811865476f;
constexpr float C_FS     = 0.17677669529663687f;
constexpr float C_FV     = 0.14433756729740643f;
constexpr float NORM_LIN = 0.05590169943749474f;
constexpr float INV_SM   = 0.25f;

__device__ __forceinline__ float silu_f(float x) { return x / (1.f + __expf(-x)); }

// ---------------- tf32 helpers ----------------
__device__ __forceinline__ float tf32r(float x) {
    uint32_t u;
    asm("cvt.rna.tf32.f32 %0, %1;" : "=r"(u) : "f"(x));
    return __uint_as_float(u);
}
__device__ __forceinline__ void mma_tf32(float& d0, float& d1, float& d2, float& d3,
                                         uint32_t a0, uint32_t a1, uint32_t a2, uint32_t a3,
                                         uint32_t b0, uint32_t b1) {
    asm volatile(
        "mma.sync.aligned.m16n8k8.row.col.f32.tf32.tf32.f32 "
        "{%0,%1,%2,%3}, {%4,%5,%6,%7}, {%8,%9}, {%0,%1,%2,%3};"
        : "+f"(d0), "+f"(d1), "+f"(d2), "+f"(d3)
        : "r"(a0), "r"(a1), "r"(a2), "r"(a3), "r"(b0), "r"(b1));
}
__device__ __forceinline__ uint32_t fbits(float x) { return __float_as_uint(x); }

// ---------------- small per-edge / per-node kernels ----------------
__global__ void k_weighter(const float* __restrict__ edge_attr, int E) {
    const int idx = blockIdx.x * blockDim.x + threadIdx.x;
    if (idx >= E * 16) return;
    const int e = idx >> 4, u = idx & 15;
    const float ws = g_w0[e * 64 + 2 * u];
    const float wv = g_w0[e * 64 + 2 * u + 1];
    g_fs[e * 16 + u] = ws * edge_attr[e * 4 + 0];
    g_fv[e * 48 + u * 3 + 0] = wv * edge_attr[e * 4 + 1];
    g_fv[e * 48 + u * 3 + 1] = wv * edge_attr[e * 4 + 2];
    g_fv[e * 48 + u * 3 + 2] = wv * edge_attr[e * 4 + 3];
}

__global__ void k_scatter(const float* __restrict__ wenv, int stride, int off,
                          const float* __restrict__ edge_attr,
                          const int* __restrict__ edge_index, int E) {
    const int idx = blockIdx.x * blockDim.x + threadIdx.x;
    if (idx >= E * 16) return;
    const int e = idx >> 4, u = idx & 15;
    const int c = edge_index[e];
    const float ws = wenv[e * stride + off + 2 * u];
    const float wv = wenv[e * stride + off + 2 * u + 1];
    atomicAdd(&g_env_s[c * 16 + u], ws * edge_attr[e * 4 + 0]);
    atomicAdd(&g_env_v[c * 48 + u * 3 + 0], wv * edge_attr[e * 4 + 1]);
    atomicAdd(&g_env_v[c * 48 + u * 3 + 1], wv * edge_attr[e * 4 + 2]);
    atomicAdd(&g_env_v[c * 48 + u * 3 + 2], wv * edge_attr[e * 4 + 3]);
}

__global__ void k_envlin(const float* __restrict__ Ws, const float* __restrict__ Wv, int N) {
    const int idx = blockIdx.x * blockDim.x + threadIdx.x;
    if (idx >= N * 16) return;
    const int n = idx >> 4, v = idx & 15;
    float s = 0.f, v0 = 0.f, v1 = 0.f, v2 = 0.f;
#pragma unroll
    for (int u = 0; u < 16; u++) {
        const float wsv = Ws[u * 16 + v];
        const float wvv = Wv[u * 16 + v];
        s  = fmaf(g_env_s[n * 16 + u], wsv, s);
        v0 = fmaf(g_env_v[n * 48 + u * 3 + 0], wvv, v0);
        v1 = fmaf(g_env_v[n * 48 + u * 3 + 1], wvv, v1);
        v2 = fmaf(g_env_v[n * 48 + u * 3 + 2], wvv, v2);
    }
    g_env_s2[n * 16 + v] = s * NORM_LIN;
    g_env_v2[n * 48 + v * 3 + 0] = v0 * NORM_LIN;
    g_env_v2[n * 48 + v * 3 + 1] = v1 * NORM_LIN;
    g_env_v2[n * 48 + v * 3 + 2] = v2 * NORM_LIN;
}

__global__ void k_combine(const int* __restrict__ edge_index, int E) {
    const int idx = blockIdx.x * blockDim.x + threadIdx.x;
    if (idx >= E * 16) return;
    const int e = idx >> 4, u = idx & 15;
    const int c = edge_index[e];
    const float es  = g_env_s2[c * 16 + u];
    const float ev0 = g_env_v2[c * 48 + u * 3 + 0];
    const float ev1 = g_env_v2[c * 48 + u * 3 + 1];
    const float ev2 = g_env_v2[c * 48 + u * 3 + 2];
    const float fsv = g_fs[e * 16 + u];
    const float fv0 = g_fv[e * 48 + u * 3 + 0];
    const float fv1 = g_fv[e * 48 + u * 3 + 1];
    const float fv2 = g_fv[e * 48 + u * 3 + 2];

    g_scal[e * 32 + 2 * u]     = fsv * es;
    g_scal[e * 32 + 2 * u + 1] = (fv0 * ev0 + fv1 * ev1 + fv2 * ev2) * INV_S3;

    float* Vp = &g_V[e * 144];
    Vp[u * 3 + 0] = fsv * ev0;
    Vp[u * 3 + 1] = fsv * ev1;
    Vp[u * 3 + 2] = fsv * ev2;
    Vp[48 + u * 3 + 0] = fv0 * es;
    Vp[48 + u * 3 + 1] = fv1 * es;
    Vp[48 + u * 3 + 2] = fv2 * es;
    Vp[96 + u * 3 + 0] = (fv1 * ev2 - fv2 * ev1) * INV_S2;
    Vp[96 + u * 3 + 1] = (fv2 * ev0 - fv0 * ev2) * INV_S2;
    Vp[96 + u * 3 + 2] = (fv0 * ev1 - fv1 * ev0) * INV_S2;
}

// ---------------- l2w weight frag-packing (plain tf32, proven in R5) ----------------
__global__ void k_pack_w1(const float* __restrict__ W1) {
    const int idx = blockIdx.x * blockDim.x + threadIdx.x;
    if (idx >= 16 * 20 * 64) return;
    const int frag = idx >> 6;
    const int r = idx & 63;
    const int lane = r >> 1, z = r & 1;
    const int ch = frag / 20, ks = frag % 20;
    const int n = ch * 8 + (lane >> 2);
    const int k = ks * 8 + (lane & 3) + z * 4;
    g_w1f[idx] = tf32r(W1[k * 128 + n]);
}
__global__ void k_pack_w2(const float* __restrict__ W2) {
    const int idx = blockIdx.x * blockDim.x + threadIdx.x;
    if (idx >= 80 * 2 * 16 * 64) return;
    const int frag = idx >> 6;
    const int r = idx & 63;
    const int lane = r >> 1, z = r & 1;
    const int puh = frag >> 4, ks = frag & 15;
    const int pu = puh >> 1, h = puh & 1;
    const int n = pu * 16 + h * 8 + (lane >> 2);
    const int k = ks * 8 + (lane & 3) + z * 4;
    g_w2f[idx] = tf32r(W2[k * 1280 + n]);
}

// ---------------- MLP weight frag-packing (hi/lo for 3xTF32) ----------------
// layout: dst[frag*128 + lane*4 + {hi_z0, hi_z1, lo_z0, lo_z1}]
// W1 frags: frag = ch*KS1+ks (N=128 fixed, ldn=128). W2 frags: ch*16+ks, ldn=OUT.
__global__ void k_pack_mlp(const float* __restrict__ W1, int KS1,
                           const float* __restrict__ W2, int NCH2, int OUT) {
    const int tid = blockIdx.x * blockDim.x + threadIdx.x;
    const int n1 = 16 * KS1;
    if (tid >= (n1 + NCH2 * 16) * 32) return;
    const int frag = tid >> 5, lane = tid & 31;
    const float* W;
    float* dst;
    int ldn, fl, ch, ks;
    if (frag < n1) {
        W = W1; ldn = 128; dst = g_mw1f; fl = frag;
        ch = fl / KS1; ks = fl - ch * KS1;
    } else {
        W = W2; ldn = OUT; dst = g_mw2f; fl = frag - n1;
        ch = fl >> 4; ks = fl & 15;
    }
    const int n = ch * 8 + (lane >> 2);
    const int k = ks * 8 + (lane & 3);
    const float w0 = W[k * ldn + n];
    const float w1 = W[(k + 4) * ldn + n];
    const float h0 = tf32r(w0), h1 = tf32r(w1);
    float4 o;
    o.x = h0; o.y = h1;
    o.z = tf32r(w0 - h0); o.w = tf32r(w1 - h1);
    *reinterpret_cast<float4*>(&dst[fl * 128 + lane * 4]) = o;
}

// ---------------- tensor-core MLP: Y = silu(X@W1)@W2, 3xTF32 (~fp32 accuracy) ----------
// 128 edges/CTA, 8 warps x 16 rows. X staged to smem; H overwrites X region
// (per-warp-private rows -> warp syncs only). B frags: one LDG.128 (hi/lo packed).
// STAGE: 0 = X=g_lat(128); 1 = X=[g_lat|g_scal](160); 2 = gather x2b(16) + cut.
// EPI:   0 = store Y;  1 = lat blend;  2 = cut-scale into g_lat.
template <int IN, int KS1, int NCH2, int STAGE, int EPI>
__global__ void __launch_bounds__(256, 1)
k_mlp_tc(const float* __restrict__ Xa, const float* __restrict__ Xb,
         const float* __restrict__ edge_u, const int* __restrict__ edge_index,
         float* __restrict__ Y, int E) {
    constexpr int XSTR = (IN >= 128) ? IN + 5 : 133;
    constexpr int OUT = NCH2 * 8;
    extern __shared__ float sm[];
    float* Xs = sm;
    const int t = threadIdx.x, lane = t & 31, w = t >> 5;
    const int g = lane >> 2, q = lane & 3;
    const int e0 = blockIdx.x * 128;

    // ---- stage X ----
    if (STAGE == 2) {
        for (int idx = t; idx < 128 * 16; idx += 256) {
            const int le = idx >> 4, c = idx & 15;
            const int e = e0 + le;
            float v = 0.f;
            if (e < E) {
                if (c < 4)       v = Xa[edge_index[e] * 4 + c];
                else if (c < 8)  v = Xa[edge_index[E + e] * 4 + (c - 4)];
                else             v = Xb[e * 8 + (c - 8)];
            }
            Xs[le * XSTR + c] = v;
        }
        if (t < 128) {
            const int e = e0 + t;
            if (e < E) {
                const float u = edge_u[e];
                const float u2 = u * u, u3 = u2 * u, u6 = u3 * u3;
                const float f = 1.f - 28.f * u6 + 48.f * u6 * u - 21.f * u6 * u2;
                g_cut[e] = (u < 1.f) ? f : 0.f;
            }
        }
    } else {
        for (int idx = t; idx < 128 * IN; idx += 256) {
            const int le = idx / IN, c = idx - le * IN;
            const int e = e0 + le;
            float v = 0.f;
            if (e < E) v = (STAGE == 0 || c < 128) ? Xa[e * 128 + c] : Xb[e * 32 + (c - 128)];
            Xs[le * XSTR + c] = v;
        }
    }
    __syncthreads();

    const int r0 = w * 16 + g;

    // ---- GEMM1: H = X @ W1 (3xTF32), acc[16 n-chunks][4] ----
    float acc[16][4];
#pragma unroll
    for (int c = 0; c < 16; c++)
#pragma unroll
        for (int j = 0; j < 4; j++) acc[c][j] = 0.f;

#pragma unroll 1
    for (int ks = 0; ks < KS1; ks++) {
        const int k0 = ks * 8;
        const float x0 = Xs[r0 * XSTR + k0 + q];
        const float x1 = Xs[(r0 + 8) * XSTR + k0 + q];
        const float x2 = Xs[r0 * XSTR + k0 + q + 4];
        const float x3 = Xs[(r0 + 8) * XSTR + k0 + q + 4];
        const float h0 = tf32r(x0), h1 = tf32r(x1), h2 = tf32r(x2), h3 = tf32r(x3);
        const uint32_t ah0 = fbits(h0), ah1 = fbits(h1), ah2 = fbits(h2), ah3 = fbits(h3);
        const uint32_t al0 = fbits(tf32r(x0 - h0)), al1 = fbits(tf32r(x1 - h1));
        const uint32_t al2 = fbits(tf32r(x2 - h2)), al3 = fbits(tf32r(x3 - h3));
#pragma unroll
        for (int ch = 0; ch < 16; ch++) {
            const float4 b = *reinterpret_cast<const float4*>(
                &g_mw1f[(ch * KS1 + ks) * 128 + lane * 4]);
            const uint32_t bh0 = fbits(b.x), bh1 = fbits(b.y);
            const uint32_t bl0 = fbits(b.z), bl1 = fbits(b.w);
            mma_tf32(acc[ch][0], acc[ch][1], acc[ch][2], acc[ch][3],
                     al0, al1, al2, al3, bh0, bh1);
            mma_tf32(acc[ch][0], acc[ch][1], acc[ch][2], acc[ch][3],
                     ah0, ah1, ah2, ah3, bl0, bl1);
            mma_tf32(acc[ch][0], acc[ch][1], acc[ch][2], acc[ch][3],
                     ah0, ah1, ah2, ah3, bh0, bh1);
        }
    }
    __syncwarp();
    // silu -> H into Xs (own rows only)
#pragma unroll
    for (int ch = 0; ch < 16; ch++) {
        const int col = ch * 8 + 2 * q;
        Xs[r0 * XSTR + col]           = silu_f(acc[ch][0]);
        Xs[r0 * XSTR + col + 1]       = silu_f(acc[ch][1]);
        Xs[(r0 + 8) * XSTR + col]     = silu_f(acc[ch][2]);
        Xs[(r0 + 8) * XSTR + col + 1] = silu_f(acc[ch][3]);
    }
    __syncwarp();

    // ---- A-frags of GEMM2 (hi/lo) in registers ----
    uint32_t Ah[16][4], Al[16][4];
#pragma unroll
    for (int ks = 0; ks < 16; ks++) {
        const int k0 = ks * 8;
        const float x0 = Xs[r0 * XSTR + k0 + q];
        const float x1 = Xs[(r0 + 8) * XSTR + k0 + q];
        const float x2 = Xs[r0 * XSTR + k0 + q + 4];
        const float x3 = Xs[(r0 + 8) * XSTR + k0 + q + 4];
        const float h0 = tf32r(x0), h1 = tf32r(x1), h2 = tf32r(x2), h3 = tf32r(x3);
        Ah[ks][0] = fbits(h0); Ah[ks][1] = fbits(h1);
        Ah[ks][2] = fbits(h2); Ah[ks][3] = fbits(h3);
        Al[ks][0] = fbits(tf32r(x0 - h0)); Al[ks][1] = fbits(tf32r(x1 - h1));
        Al[ks][2] = fbits(tf32r(x2 - h2)); Al[ks][3] = fbits(tf32r(x3 - h3));
    }

    // ---- GEMM2 + epilogue ----
    const int er0 = e0 + r0, er8 = er0 + 8;
    float cut0 = 0.f, cut8 = 0.f;
    if (EPI != 0) {
        cut0 = (er0 < E) ? g_cut[er0] : 0.f;
        cut8 = (er8 < E) ? g_cut[er8] : 0.f;
    }
#pragma unroll 1
    for (int ch = 0; ch < NCH2; ch++) {
        float d0 = 0.f, d1 = 0.f, d2 = 0.f, d3 = 0.f;
#pragma unroll
        for (int ks = 0; ks < 16; ks++) {
            const float4 b = *reinterpret_cast<const float4*>(
                &g_mw2f[(ch * 16 + ks) * 128 + lane * 4]);
            const uint32_t bh0 = fbits(b.x), bh1 = fbits(b.y);
            const uint32_t bl0 = fbits(b.z), bl1 = fbits(b.w);
            mma_tf32(d0, d1, d2, d3, Al[ks][0], Al[ks][1], Al[ks][2], Al[ks][3], bh0, bh1);
            mma_tf32(d0, d1, d2, d3, Ah[ks][0], Ah[ks][1], Ah[ks][2], Ah[ks][3], bl0, bl1);
            mma_tf32(d0, d1, d2, d3, Ah[ks][0], Ah[ks][1], Ah[ks][2], Ah[ks][3], bh0, bh1);
        }
        const int n0 = ch * 8 + 2 * q;
        if (EPI == 0) {
            if (er0 < E) { Y[er0 * OUT + n0] = d0; Y[er0 * OUT + n0 + 1] = d1; }
            if (er8 < E) { Y[er8 * OUT + n0] = d2; Y[er8 * OUT + n0 + 1] = d3; }
        } else if (EPI == 1) {
            if (er0 < E) {
                float* p = &g_lat[er0 * 128 + n0];
                p[0] = C_OLD * p[0] + A_C_OLD * cut0 * d0;
                p[1] = C_OLD * p[1] + A_C_OLD * cut0 * d1;
            }
            if (er8 < E) {
                float* p = &g_lat[er8 * 128 + n0];
                p[0] = C_OLD * p[0] + A_C_OLD * cut8 * d2;
                p[1] = C_OLD * p[1] + A_C_OLD * cut8 * d3;
            }
        } else {
            if (er0 < E) {
                g_lat[er0 * 128 + n0]     = cut0 * d0;
                g_lat[er0 * 128 + n0 + 1] = cut0 * d1;
            }
            if (er8 < E) {
                g_lat[er8 * 128 + n0]     = cut8 * d2;
                g_lat[er8 * 128 + n0 + 1] = cut8 * d3;
            }
        }
    }
}

// ---------------- mma.sync tf32 fused l2w (unchanged from R5) ----------------
#define H_STR  132
#define SM_SS  (256 * H_STR)
#define SM_VS  (SM_SS + 256 * 33)
#define L2W_SMEM_B ((SM_VS + 256 * 25) * 4)

__device__ __forceinline__ float l2w_xval(int e, int k, int E) {
    if (e >= E) return 0.f;
    const float v = (k < 128) ? g_lat[e * 128 + k] : g_scal[e * 32 + (k - 128)];
    return tf32r(v);
}

__global__ void __launch_bounds__(256, 1)
k_l2w_ts(int E) {
    extern __shared__ float sm[];
    float* Hs = sm;
    float* Ss = sm + SM_SS;
    float* Vs = sm + SM_VS;
    const int t = threadIdx.x, lane = t & 31, w = t >> 5;
    const int g = lane >> 2, q = lane & 3;
    const int e0 = blockIdx.x * 256;
    const int rb = w * 32;

    for (int idx = t; idx < 256 * 32; idx += 256) {
        const int el = idx >> 5, pu = idx & 31;
        const int e = e0 + el;
        Ss[el * 33 + pu] = (e < E) ? g_scal[e * 32 + 2 * (pu & 15) + (pu >> 4)] : 0.f;
    }
    __syncthreads();

    {
        float acc[16][8];
#pragma unroll
        for (int c = 0; c < 16; c++)
#pragma unroll
            for (int j = 0; j < 8; j++) acc[c][j] = 0.f;

#pragma unroll 1
        for (int ks = 0; ks < 20; ks++) {
            const int k0 = ks * 8;
            uint32_t a[2][4];
#pragma unroll
            for (int m = 0; m < 2; m++) {
                const int er0 = e0 + rb + 16 * m + g;
                a[m][0] = fbits(l2w_xval(er0,     k0 + q,     E));
                a[m][1] = fbits(l2w_xval(er0 + 8, k0 + q,     E));
                a[m][2] = fbits(l2w_xval(er0,     k0 + q + 4, E));
                a[m][3] = fbits(l2w_xval(er0 + 8, k0 + q + 4, E));
            }
#pragma unroll
            for (int ch = 0; ch < 16; ch++) {
                const float2 b = *reinterpret_cast<const float2*>(
                    &g_w1f[(ch * 20 + ks) * 64 + lane * 2]);
                mma_tf32(acc[ch][0], acc[ch][1], acc[ch][2], acc[ch][3],
                         a[0][0], a[0][1], a[0][2], a[0][3], fbits(b.x), fbits(b.y));
                mma_tf32(acc[ch][4], acc[ch][5], acc[ch][6], acc[ch][7],
                         a[1][0], a[1][1], a[1][2], a[1][3], fbits(b.x), fbits(b.y));
            }
        }
#pragma unroll
        for (int ch = 0; ch < 16; ch++) {
#pragma unroll
            for (int m = 0; m < 2; m++)
#pragma unroll
                for (int s = 0; s < 2; s++) {
                    const int row = rb + 16 * m + 8 * s + g;
                    const int col = ch * 8 + 2 * q;
                    Hs[row * H_STR + col]     = tf32r(silu_f(acc[ch][4 * m + 2 * s + 0]));
                    Hs[row * H_STR + col + 1] = tf32r(silu_f(acc[ch][4 * m + 2 * s + 1]));
                }
        }
        __syncwarp();
    }

    uint32_t Af[16][2][4];
#pragma unroll
    for (int ks = 0; ks < 16; ks++) {
        const int k0 = ks * 8;
#pragma unroll
        for (int m = 0; m < 2; m++) {
            const int r0 = rb + 16 * m + g;
            Af[ks][m][0] = fbits(Hs[r0 * H_STR + k0 + q]);
            Af[ks][m][1] = fbits(Hs[(r0 + 8) * H_STR + k0 + q]);
            Af[ks][m][2] = fbits(Hs[r0 * H_STR + k0 + q + 4]);
            Af[ks][m][3] = fbits(Hs[(r0 + 8) * H_STR + k0 + q + 4]);
        }
    }

    float fs[4][2][2];
    float fv[4][2][2][3];
#pragma unroll
    for (int rg = 0; rg < 4; rg++)
#pragma unroll
        for (int h = 0; h < 2; h++)
#pragma unroll
            for (int c = 0; c < 2; c++) {
                fs[rg][h][c] = 0.f;
                fv[rg][h][c][0] = 0.f; fv[rg][h][c][1] = 0.f; fv[rg][h][c][2] = 0.f;
            }

#pragma unroll 1
    for (int blk = 0; blk < 10; blk++) {
        if (blk >= 4) {
            __syncthreads();
            const int pb3 = (blk - 4) * 24;
            for (int idx = t; idx < 256 * 24; idx += 256) {
                const int el = idx / 24, c = idx - el * 24;
                const int e = e0 + el;
                Vs[el * 25 + c] = (e < E) ? g_V[e * 144 + pb3 + c] : 0.f;
            }
            __syncthreads();
        }
#pragma unroll 1
        for (int j = 0; j < 8; j++) {
            const int pu = blk * 8 + j;
#pragma unroll
            for (int h = 0; h < 2; h++) {
                float d[8];
#pragma unroll
                for (int x = 0; x < 8; x++) d[x] = 0.f;
                const int fb = ((pu * 2 + h) * 16) * 64;
#pragma unroll
                for (int ks = 0; ks < 16; ks++) {
                    const float2 b = *reinterpret_cast<const float2*>(
                        &g_w2f[fb + ks * 64 + lane * 2]);
                    mma_tf32(d[0], d[1], d[2], d[3],
                             Af[ks][0][0], Af[ks][0][1], Af[ks][0][2], Af[ks][0][3],
                             fbits(b.x), fbits(b.y));
                    mma_tf32(d[4], d[5], d[6], d[7],
                             Af[ks][1][0], Af[ks][1][1], Af[ks][1][2], Af[ks][1][3],
                             fbits(b.x), fbits(b.y));
                }
                if (blk < 4) {
#pragma unroll
                    for (int rg = 0; rg < 4; rg++) {
                        const float s = Ss[(rb + rg * 8 + g) * 33 + pu];
                        fs[rg][h][0] = fmaf(s, d[2 * rg + 0], fs[rg][h][0]);
                        fs[rg][h][1] = fmaf(s, d[2 * rg + 1], fs[rg][h][1]);
                    }
                } else {
#pragma unroll
                    for (int rg = 0; rg < 4; rg++) {
                        const int base = (rb + rg * 8 + g) * 25 + j * 3;
                        const float v0 = Vs[base], v1 = Vs[base + 1], v2 = Vs[base + 2];
#pragma unroll
                        for (int c = 0; c < 2; c++) {
                            const float dd = d[2 * rg + c];
                            fv[rg][h][c][0] = fmaf(dd, v0, fv[rg][h][c][0]);
                            fv[rg][h][c][1] = fmaf(dd, v1, fv[rg][h][c][1]);
                            fv[rg][h][c][2] = fmaf(dd, v2, fv[rg][h][c][2]);
                        }
                    }
                }
            }
        }
    }

#pragma unroll
    for (int rg = 0; rg < 4; rg++) {
        const int e = e0 + rb + rg * 8 + g;
        if (e >= E) continue;
#pragma unroll
        for (int h = 0; h < 2; h++)
#pragma unroll
            for (int c = 0; c < 2; c++) {
                const int v = h * 8 + 2 * q + c;
                g_fs[e * 16 + v] = C_FS * fs[rg][h][c];
                g_fv[e * 48 + v * 3 + 0] = C_FV * fv[rg][h][c][0];
                g_fv[e * 48 + v * 3 + 1] = C_FV * fv[rg][h][c][1];
                g_fv[e * 48 + v * 3 + 2] = C_FV * fv[rg][h][c][2];
            }
    }
}

// ---------------- final output ----------------
__global__ void k_out(float* __restrict__ out, int E) {
    const int idx = blockIdx.x * blockDim.x + threadIdx.x;
    if (idx >= E * 3) return;
    const int e = idx / 3, i = idx - e * 3;
    float acc = 0.f;
#pragma unroll
    for (int u = 0; u < 16; u++)
        acc = fmaf(g_wenv1[e * 16 + u], g_fv[e * 48 + u * 3 + i], acc);
    out[idx] = INV_SM * acc;
}

// ---------------- host driver ----------------
extern "C" void kernel_launch(void* const* d_in, const int* in_sizes, int n_in,
                              void* d_out, int out_size) {
    const float* edge_attr  = (const float*)d_in[0];
    const float* node_attrs = (const float*)d_in[1];
    const float* edge_embed = (const float*)d_in[2];
    const float* edge_u     = (const float*)d_in[3];
    const int*   edge_index = (const int*)d_in[4];
    const float* w2b1    = (const float*)d_in[5];
    const float* w2b2    = (const float*)d_in[6];
    const float* lat1_w1 = (const float*)d_in[7];
    const float* lat1_w2 = (const float*)d_in[8];
    const float* env0_w1 = (const float*)d_in[9];
    const float* env0_w2 = (const float*)d_in[10];
    const float* env1_w1 = (const float*)d_in[11];
    const float* env1_w2 = (const float*)d_in[12];
    const float* l2w0_w1 = (const float*)d_in[13];
    const float* l2w0_w2 = (const float*)d_in[14];
    const float* l2w1_w1 = (const float*)d_in[15];
    const float* l2w1_w2 = (const float*)d_in[16];
    const float* envlin_ws = (const float*)d_in[17];
    const float* envlin_wv = (const float*)d_in[18];
    const float* fl2w_w1 = (const float*)d_in[19];
    const float* fl2w_w2 = (const float*)d_in[20];
    float* out = (float*)d_out;

    const int E = in_sizes[0] / 4;
    const int N = in_sizes[1] / 4;
    if (E > MAX_E || N > MAX_N) return;

    float *p_lat, *p_scal, *p_w0, *p_wenv1, *p_env_s, *p_env_v;
    cudaGetSymbolAddress((void**)&p_lat, g_lat);
    cudaGetSymbolAddress((void**)&p_scal, g_scal);
    cudaGetSymbolAddress((void**)&p_w0, g_w0);
    cudaGetSymbolAddress((void**)&p_wenv1, g_wenv1);
    cudaGetSymbolAddress((void**)&p_env_s, g_env_s);
    cudaGetSymbolAddress((void**)&p_env_v, g_env_v);

    // smem sizes for MLP kernels: stride = IN+5 (IN>=128) or 133
    const int smM160 = 128 * 165 * 4;   // 84480
    const int smM128 = 128 * 133 * 4;   // 68096

    cudaFuncSetAttribute((const void*)k_mlp_tc<16, 2,16,2,2>, cudaFuncAttributeMaxDynamicSharedMemorySize, smM128);
    cudaFuncSetAttribute((const void*)k_mlp_tc<128,16, 8,0,0>, cudaFuncAttributeMaxDynamicSharedMemorySize, smM128);
    cudaFuncSetAttribute((const void*)k_mlp_tc<160,20,16,1,1>, cudaFuncAttributeMaxDynamicSharedMemorySize, smM160);
    cudaFuncSetAttribute((const void*)k_mlp_tc<128,16, 4,0,0>, cudaFuncAttributeMaxDynamicSharedMemorySize, smM128);
    cudaFuncSetAttribute((const void*)k_mlp_tc<160,20, 2,1,0>, cudaFuncAttributeMaxDynamicSharedMemorySize, smM160);
    cudaFuncSetAttribute((const void*)k_l2w_ts, cudaFuncAttributeMaxDynamicSharedMemorySize, L2W_SMEM_B);

    const int nbM   = (E + 127) / 128;
    const int nb256 = (E + 255) / 256;
    const int nb16  = (E * 16 + 255) / 256;

    auto packN = [](int KS1, int NCH2) { return ((16 * KS1 + NCH2 * 16) * 32 + 255) / 256; };

    // ---- stage 0: first MLP (gather, cut-scale epi) + env0 ----
    k_pack_mlp<<<packN(2, 16), 256>>>(w2b1, 2, w2b2, 16, 128);
    k_mlp_tc<16, 2,16,2,2><<<nbM, 256, smM128>>>(node_attrs, edge_embed, edge_u, edge_index, p_lat, E);
    k_pack_mlp<<<packN(16, 8), 256>>>(env0_w1, 16, env0_w2, 8, 64);
    k_mlp_tc<128,16, 8,0,0><<<nbM, 256, smM128>>>(p_lat, p_lat, edge_u, edge_index, p_w0, E);
    k_weighter<<<nb16, 256>>>(edge_attr, E);

    // ---- layer 0 ----
    cudaMemsetAsync(p_env_s, 0, (size_t)N * 16 * sizeof(float));
    cudaMemsetAsync(p_env_v, 0, (size_t)N * 48 * sizeof(float));
    k_scatter<<<nb16, 256>>>(p_w0, 64, 32, edge_attr, edge_index, E);
    k_envlin<<<(N * 16 + 255) / 256, 256>>>(envlin_ws, envlin_wv, N);
    k_combine<<<nb16, 256>>>(edge_index, E);
    k_pack_w1<<<(16 * 20 * 64 + 255) / 256, 256>>>(l2w0_w1);
    k_pack_w2<<<(80 * 2 * 16 * 64 + 255) / 256, 256>>>(l2w0_w2);
    k_l2w_ts<<<nb256, 256, L2W_SMEM_B>>>(E);

    // ---- layer 1 ----
    k_pack_mlp<<<packN(20, 16), 256>>>(lat1_w1, 20, lat1_w2, 16, 128);
    k_mlp_tc<160,20,16,1,1><<<nbM, 256, smM160>>>(p_lat, p_scal, edge_u, edge_index, p_lat, E);
    k_pack_mlp<<<packN(16, 4), 256>>>(env1_w1, 16, env1_w2, 4, 32);
    k_mlp_tc<128,16, 4,0,0><<<nbM, 256, smM128>>>(p_lat, p_lat, edge_u, edge_index, p_wenv1, E);
    cudaMemsetAsync(p_env_s, 0, (size_t)N * 16 * sizeof(float));
    cudaMemsetAsync(p_env_v, 0, (size_t)N * 48 * sizeof(float));
    k_scatter<<<nb16, 256>>>(p_wenv1, 32, 0, edge_attr, edge_index, E);
    k_envlin<<<(N * 16 + 255) / 256, 256>>>(envlin_ws + 256, envlin_wv + 256, N);
    k_combine<<<nb16, 256>>>(edge_index, E);
    k_pack_w1<<<(16 * 20 * 64 + 255) / 256, 256>>>(l2w1_w1);
    k_pack_w2<<<(80 * 2 * 16 * 64 + 255) / 256, 256>>>(l2w1_w2);
    k_l2w_ts<<<nb256, 256, L2W_SMEM_B>>>(E);

    // ---- final: fw MLP + contraction ----
    k_pack_mlp<<<packN(20, 2), 256>>>(fl2w_w1, 20, fl2w_w2, 2, 16);
    k_mlp_tc<160,20, 2,1,0><<<nbM, 256, smM160>>>(p_lat, p_scal, edge_u, edge_index, p_wenv1, E);
    k_out<<<(E * 3 + 255) / 256, 256>>>(out, E);
}

// round 7
// speedup vs baseline: 2.7958x; 1.1873x over previous
#include <cuda_runtime.h>
#include <cstdint>

// ---------------- problem constants ----------------
#define MAX_E 120000
#define MAX_N 5000

typedef unsigned long long u64;

// ---------------- scratch (static __device__, allocation-free) ----------------
__device__ float g_cut[MAX_E];
__device__ float g_lat[MAX_E * 128];
__device__ float g_w0[MAX_E * 64];
__device__ float g_wenv1[MAX_E * 32];
__device__ float g_fs[MAX_E * 16];
__device__ float g_fv[MAX_E * 48];
__device__ float g_scal[MAX_E * 32];
__device__ float g_V[MAX_E * 144];
__device__ float g_env_s[MAX_N * 16];
__device__ float g_env_v[MAX_N * 48];
__device__ float g_env_s2[MAX_N * 16];
__device__ float g_env_v2[MAX_N * 48];
__device__ float g_w1f[16 * 20 * 64];      // l2w W1 frag-packed (plain tf32)
__device__ float g_w2f[80 * 2 * 16 * 64];  // l2w W2 frag-packed (plain tf32)
__device__ float g_mw1f[16 * 20 * 128];    // MLP W1 frag-packed hi/lo
__device__ float g_mw2f[16 * 16 * 128];    // MLP W2 frag-packed hi/lo

// ---------------- math constants ----------------
constexpr float C_OLD    = 0.8944271909999159f;
constexpr float A_C_OLD  = 0.4472135954999579f;
constexpr float INV_S3   = 0.5773502691896258f;
constexpr float INV_S2   = 0.7071067811865476f;
constexpr float C_FS     = 0.17677669529663687f;
constexpr float C_FV     = 0.14433756729740643f;
constexpr float NORM_LIN = 0.05590169943749474f;
constexpr float INV_SM   = 0.25f;

__device__ __forceinline__ float silu_f(float x) { return x / (1.f + __expf(-x)); }

// ---------------- tf32 helpers ----------------
__device__ __forceinline__ float tf32r(float x) {
    uint32_t u;
    asm("cvt.rna.tf32.f32 %0, %1;" : "=r"(u) : "f"(x));
    return __uint_as_float(u);
}
__device__ __forceinline__ void mma_tf32(float& d0, float& d1, float& d2, float& d3,
                                         uint32_t a0, uint32_t a1, uint32_t a2, uint32_t a3,
                                         uint32_t b0, uint32_t b1) {
    asm volatile(
        "mma.sync.aligned.m16n8k8.row.col.f32.tf32.tf32.f32 "
        "{%0,%1,%2,%3}, {%4,%5,%6,%7}, {%8,%9}, {%0,%1,%2,%3};"
        : "+f"(d0), "+f"(d1), "+f"(d2), "+f"(d3)
        : "r"(a0), "r"(a1), "r"(a2), "r"(a3), "r"(b0), "r"(b1));
}
__device__ __forceinline__ uint32_t fbits(float x) { return __float_as_uint(x); }

// ---------------- small per-edge / per-node kernels ----------------
__global__ void k_weighter(const float* __restrict__ edge_attr, int E) {
    const int idx = blockIdx.x * blockDim.x + threadIdx.x;
    if (idx >= E * 16) return;
    const int e = idx >> 4, u = idx & 15;
    const float ws = g_w0[e * 64 + 2 * u];
    const float wv = g_w0[e * 64 + 2 * u + 1];
    g_fs[e * 16 + u] = ws * edge_attr[e * 4 + 0];
    g_fv[e * 48 + u * 3 + 0] = wv * edge_attr[e * 4 + 1];
    g_fv[e * 48 + u * 3 + 1] = wv * edge_attr[e * 4 + 2];
    g_fv[e * 48 + u * 3 + 2] = wv * edge_attr[e * 4 + 3];
}

__global__ void k_scatter(const float* __restrict__ wenv, int stride, int off,
                          const float* __restrict__ edge_attr,
                          const int* __restrict__ edge_index, int E) {
    const int idx = blockIdx.x * blockDim.x + threadIdx.x;
    if (idx >= E * 16) return;
    const int e = idx >> 4, u = idx & 15;
    const int c = edge_index[e];
    const float ws = wenv[e * stride + off + 2 * u];
    const float wv = wenv[e * stride + off + 2 * u + 1];
    atomicAdd(&g_env_s[c * 16 + u], ws * edge_attr[e * 4 + 0]);
    atomicAdd(&g_env_v[c * 48 + u * 3 + 0], wv * edge_attr[e * 4 + 1]);
    atomicAdd(&g_env_v[c * 48 + u * 3 + 1], wv * edge_attr[e * 4 + 2]);
    atomicAdd(&g_env_v[c * 48 + u * 3 + 2], wv * edge_attr[e * 4 + 3]);
}

__global__ void k_envlin(const float* __restrict__ Ws, const float* __restrict__ Wv, int N) {
    const int idx = blockIdx.x * blockDim.x + threadIdx.x;
    if (idx >= N * 16) return;
    const int n = idx >> 4, v = idx & 15;
    float s = 0.f, v0 = 0.f, v1 = 0.f, v2 = 0.f;
#pragma unroll
    for (int u = 0; u < 16; u++) {
        const float wsv = Ws[u * 16 + v];
        const float wvv = Wv[u * 16 + v];
        s  = fmaf(g_env_s[n * 16 + u], wsv, s);
        v0 = fmaf(g_env_v[n * 48 + u * 3 + 0], wvv, v0);
        v1 = fmaf(g_env_v[n * 48 + u * 3 + 1], wvv, v1);
        v2 = fmaf(g_env_v[n * 48 + u * 3 + 2], wvv, v2);
    }
    g_env_s2[n * 16 + v] = s * NORM_LIN;
    g_env_v2[n * 48 + v * 3 + 0] = v0 * NORM_LIN;
    g_env_v2[n * 48 + v * 3 + 1] = v1 * NORM_LIN;
    g_env_v2[n * 48 + v * 3 + 2] = v2 * NORM_LIN;
}

__global__ void k_combine(const int* __restrict__ edge_index, int E) {
    const int idx = blockIdx.x * blockDim.x + threadIdx.x;
    if (idx >= E * 16) return;
    const int e = idx >> 4, u = idx & 15;
    const int c = edge_index[e];
    const float es  = g_env_s2[c * 16 + u];
    const float ev0 = g_env_v2[c * 48 + u * 3 + 0];
    const float ev1 = g_env_v2[c * 48 + u * 3 + 1];
    const float ev2 = g_env_v2[c * 48 + u * 3 + 2];
    const float fsv = g_fs[e * 16 + u];
    const float fv0 = g_fv[e * 48 + u * 3 + 0];
    const float fv1 = g_fv[e * 48 + u * 3 + 1];
    const float fv2 = g_fv[e * 48 + u * 3 + 2];

    g_scal[e * 32 + 2 * u]     = fsv * es;
    g_scal[e * 32 + 2 * u + 1] = (fv0 * ev0 + fv1 * ev1 + fv2 * ev2) * INV_S3;

    float* Vp = &g_V[e * 144];
    Vp[u * 3 + 0] = fsv * ev0;
    Vp[u * 3 + 1] = fsv * ev1;
    Vp[u * 3 + 2] = fsv * ev2;
    Vp[48 + u * 3 + 0] = fv0 * es;
    Vp[48 + u * 3 + 1] = fv1 * es;
    Vp[48 + u * 3 + 2] = fv2 * es;
    Vp[96 + u * 3 + 0] = (fv1 * ev2 - fv2 * ev1) * INV_S2;
    Vp[96 + u * 3 + 1] = (fv2 * ev0 - fv0 * ev2) * INV_S2;
    Vp[96 + u * 3 + 2] = (fv0 * ev1 - fv1 * ev0) * INV_S2;
}

// ---------------- l2w weight frag-packing (plain tf32, proven in R5) ----------------
__global__ void k_pack_w1(const float* __restrict__ W1) {
    const int idx = blockIdx.x * blockDim.x + threadIdx.x;
    if (idx >= 16 * 20 * 64) return;
    const int frag = idx >> 6;
    const int r = idx & 63;
    const int lane = r >> 1, z = r & 1;
    const int ch = frag / 20, ks = frag % 20;
    const int n = ch * 8 + (lane >> 2);
    const int k = ks * 8 + (lane & 3) + z * 4;
    g_w1f[idx] = tf32r(W1[k * 128 + n]);
}
__global__ void k_pack_w2(const float* __restrict__ W2) {
    const int idx = blockIdx.x * blockDim.x + threadIdx.x;
    if (idx >= 80 * 2 * 16 * 64) return;
    const int frag = idx >> 6;
    const int r = idx & 63;
    const int lane = r >> 1, z = r & 1;
    const int puh = frag >> 4, ks = frag & 15;
    const int pu = puh >> 1, h = puh & 1;
    const int n = pu * 16 + h * 8 + (lane >> 2);
    const int k = ks * 8 + (lane & 3) + z * 4;
    g_w2f[idx] = tf32r(W2[k * 1280 + n]);
}

// ---------------- MLP weight frag-packing (hi/lo for 3xTF32) ----------------
__global__ void k_pack_mlp(const float* __restrict__ W1, int KS1,
                           const float* __restrict__ W2, int NCH2, int OUT) {
    const int tid = blockIdx.x * blockDim.x + threadIdx.x;
    const int n1 = 16 * KS1;
    if (tid >= (n1 + NCH2 * 16) * 32) return;
    const int frag = tid >> 5, lane = tid & 31;
    const float* W;
    float* dst;
    int ldn, fl, ch, ks;
    if (frag < n1) {
        W = W1; ldn = 128; dst = g_mw1f; fl = frag;
        ch = fl / KS1; ks = fl - ch * KS1;
    } else {
        W = W2; ldn = OUT; dst = g_mw2f; fl = frag - n1;
        ch = fl >> 4; ks = fl & 15;
    }
    const int n = ch * 8 + (lane >> 2);
    const int k = ks * 8 + (lane & 3);
    const float w0 = W[k * ldn + n];
    const float w1 = W[(k + 4) * ldn + n];
    const float h0 = tf32r(w0), h1 = tf32r(w1);
    float4 o;
    o.x = h0; o.y = h1;
    o.z = tf32r(w0 - h0); o.w = tf32r(w1 - h1);
    *reinterpret_cast<float4*>(&dst[fl * 128 + lane * 4]) = o;
}

// ---------------- tensor-core MLP: Y = silu(X@W1)@W2, 3xTF32 ----------
// R7: GEMM2 loop-reordered (ks outer, ch inner, per-ch accumulators) so no
// A-fragment arrays are held live -> regs <= 128 -> 2 CTAs/SM (occ 25%).
template <int IN, int KS1, int NCH2, int STAGE, int EPI>
__global__ void __launch_bounds__(256, 2)
k_mlp_tc(const float* __restrict__ Xa, const float* __restrict__ Xb,
         const float* __restrict__ edge_u, const int* __restrict__ edge_index,
         float* __restrict__ Y, int E) {
    constexpr int XSTR = (IN >= 128) ? IN + 5 : 133;
    constexpr int OUT = NCH2 * 8;
    extern __shared__ float sm[];
    float* Xs = sm;
    const int t = threadIdx.x, lane = t & 31, w = t >> 5;
    const int g = lane >> 2, q = lane & 3;
    const int e0 = blockIdx.x * 128;

    // ---- stage X ----
    if (STAGE == 2) {
        for (int idx = t; idx < 128 * 16; idx += 256) {
            const int le = idx >> 4, c = idx & 15;
            const int e = e0 + le;
            float v = 0.f;
            if (e < E) {
                if (c < 4)       v = Xa[edge_index[e] * 4 + c];
                else if (c < 8)  v = Xa[edge_index[E + e] * 4 + (c - 4)];
                else             v = Xb[e * 8 + (c - 8)];
            }
            Xs[le * XSTR + c] = v;
        }
        if (t < 128) {
            const int e = e0 + t;
            if (e < E) {
                const float u = edge_u[e];
                const float u2 = u * u, u3 = u2 * u, u6 = u3 * u3;
                const float f = 1.f - 28.f * u6 + 48.f * u6 * u - 21.f * u6 * u2;
                g_cut[e] = (u < 1.f) ? f : 0.f;
            }
        }
    } else {
        for (int idx = t; idx < 128 * IN; idx += 256) {
            const int le = idx / IN, c = idx - le * IN;
            const int e = e0 + le;
            float v = 0.f;
            if (e < E) v = (STAGE == 0 || c < 128) ? Xa[e * 128 + c] : Xb[e * 32 + (c - 128)];
            Xs[le * XSTR + c] = v;
        }
    }
    __syncthreads();

    const int r0 = w * 16 + g;

    // ---- GEMM1: H = X @ W1 (3xTF32), ks outer / ch inner ----
    {
        float acc[16][4];
#pragma unroll
        for (int c = 0; c < 16; c++)
#pragma unroll
            for (int j = 0; j < 4; j++) acc[c][j] = 0.f;

#pragma unroll 1
        for (int ks = 0; ks < KS1; ks++) {
            const int k0 = ks * 8;
            const float x0 = Xs[r0 * XSTR + k0 + q];
            const float x1 = Xs[(r0 + 8) * XSTR + k0 + q];
            const float x2 = Xs[r0 * XSTR + k0 + q + 4];
            const float x3 = Xs[(r0 + 8) * XSTR + k0 + q + 4];
            const float h0 = tf32r(x0), h1 = tf32r(x1), h2 = tf32r(x2), h3 = tf32r(x3);
            const uint32_t ah0 = fbits(h0), ah1 = fbits(h1), ah2 = fbits(h2), ah3 = fbits(h3);
            const uint32_t al0 = fbits(tf32r(x0 - h0)), al1 = fbits(tf32r(x1 - h1));
            const uint32_t al2 = fbits(tf32r(x2 - h2)), al3 = fbits(tf32r(x3 - h3));
#pragma unroll
            for (int ch = 0; ch < 16; ch++) {
                const float4 b = *reinterpret_cast<const float4*>(
                    &g_mw1f[(ch * KS1 + ks) * 128 + lane * 4]);
                const uint32_t bh0 = fbits(b.x), bh1 = fbits(b.y);
                const uint32_t bl0 = fbits(b.z), bl1 = fbits(b.w);
                mma_tf32(acc[ch][0], acc[ch][1], acc[ch][2], acc[ch][3],
                         al0, al1, al2, al3, bh0, bh1);
                mma_tf32(acc[ch][0], acc[ch][1], acc[ch][2], acc[ch][3],
                         ah0, ah1, ah2, ah3, bl0, bl1);
                mma_tf32(acc[ch][0], acc[ch][1], acc[ch][2], acc[ch][3],
                         ah0, ah1, ah2, ah3, bh0, bh1);
            }
        }
        __syncwarp();
        // silu -> H into Xs (own rows only)
#pragma unroll
        for (int ch = 0; ch < 16; ch++) {
            const int col = ch * 8 + 2 * q;
            Xs[r0 * XSTR + col]           = silu_f(acc[ch][0]);
            Xs[r0 * XSTR + col + 1]       = silu_f(acc[ch][1]);
            Xs[(r0 + 8) * XSTR + col]     = silu_f(acc[ch][2]);
            Xs[(r0 + 8) * XSTR + col + 1] = silu_f(acc[ch][3]);
        }
        __syncwarp();
    }

    // ---- GEMM2: ks outer / ch inner, per-ch accumulators (no A-frag arrays) ----
    float acc2[NCH2][4];
#pragma unroll
    for (int c = 0; c < NCH2; c++)
#pragma unroll
        for (int j = 0; j < 4; j++) acc2[c][j] = 0.f;

#pragma unroll 1
    for (int ks = 0; ks < 16; ks++) {
        const int k0 = ks * 8;
        const float x0 = Xs[r0 * XSTR + k0 + q];
        const float x1 = Xs[(r0 + 8) * XSTR + k0 + q];
        const float x2 = Xs[r0 * XSTR + k0 + q + 4];
        const float x3 = Xs[(r0 + 8) * XSTR + k0 + q + 4];
        const float h0 = tf32r(x0), h1 = tf32r(x1), h2 = tf32r(x2), h3 = tf32r(x3);
        const uint32_t ah0 = fbits(h0), ah1 = fbits(h1), ah2 = fbits(h2), ah3 = fbits(h3);
        const uint32_t al0 = fbits(tf32r(x0 - h0)), al1 = fbits(tf32r(x1 - h1));
        const uint32_t al2 = fbits(tf32r(x2 - h2)), al3 = fbits(tf32r(x3 - h3));
#pragma unroll
        for (int ch = 0; ch < NCH2; ch++) {
            const float4 b = *reinterpret_cast<const float4*>(
                &g_mw2f[(ch * 16 + ks) * 128 + lane * 4]);
            const uint32_t bh0 = fbits(b.x), bh1 = fbits(b.y);
            const uint32_t bl0 = fbits(b.z), bl1 = fbits(b.w);
            mma_tf32(acc2[ch][0], acc2[ch][1], acc2[ch][2], acc2[ch][3],
                     al0, al1, al2, al3, bh0, bh1);
            mma_tf32(acc2[ch][0], acc2[ch][1], acc2[ch][2], acc2[ch][3],
                     ah0, ah1, ah2, ah3, bl0, bl1);
            mma_tf32(acc2[ch][0], acc2[ch][1], acc2[ch][2], acc2[ch][3],
                     ah0, ah1, ah2, ah3, bh0, bh1);
        }
    }

    // ---- epilogue ----
    const int er0 = e0 + r0, er8 = er0 + 8;
    float cut0 = 0.f, cut8 = 0.f;
    if (EPI != 0) {
        cut0 = (er0 < E) ? g_cut[er0] : 0.f;
        cut8 = (er8 < E) ? g_cut[er8] : 0.f;
    }
#pragma unroll
    for (int ch = 0; ch < NCH2; ch++) {
        const int n0 = ch * 8 + 2 * q;
        const float d0 = acc2[ch][0], d1 = acc2[ch][1];
        const float d2 = acc2[ch][2], d3 = acc2[ch][3];
        if (EPI == 0) {
            if (er0 < E) { Y[er0 * OUT + n0] = d0; Y[er0 * OUT + n0 + 1] = d1; }
            if (er8 < E) { Y[er8 * OUT + n0] = d2; Y[er8 * OUT + n0 + 1] = d3; }
        } else if (EPI == 1) {
            if (er0 < E) {
                float* p = &g_lat[er0 * 128 + n0];
                p[0] = C_OLD * p[0] + A_C_OLD * cut0 * d0;
                p[1] = C_OLD * p[1] + A_C_OLD * cut0 * d1;
            }
            if (er8 < E) {
                float* p = &g_lat[er8 * 128 + n0];
                p[0] = C_OLD * p[0] + A_C_OLD * cut8 * d2;
                p[1] = C_OLD * p[1] + A_C_OLD * cut8 * d3;
            }
        } else {
            if (er0 < E) {
                g_lat[er0 * 128 + n0]     = cut0 * d0;
                g_lat[er0 * 128 + n0 + 1] = cut0 * d1;
            }
            if (er8 < E) {
                g_lat[er8 * 128 + n0]     = cut8 * d2;
                g_lat[er8 * 128 + n0 + 1] = cut8 * d3;
            }
        }
    }
}

// ---------------- mma.sync tf32 fused l2w (unchanged from R5) ----------------
#define H_STR  132
#define SM_SS  (256 * H_STR)
#define SM_VS  (SM_SS + 256 * 33)
#define L2W_SMEM_B ((SM_VS + 256 * 25) * 4)

__device__ __forceinline__ float l2w_xval(int e, int k, int E) {
    if (e >= E) return 0.f;
    const float v = (k < 128) ? g_lat[e * 128 + k] : g_scal[e * 32 + (k - 128)];
    return tf32r(v);
}

__global__ void __launch_bounds__(256, 1)
k_l2w_ts(int E) {
    extern __shared__ float sm[];
    float* Hs = sm;
    float* Ss = sm + SM_SS;
    float* Vs = sm + SM_VS;
    const int t = threadIdx.x, lane = t & 31, w = t >> 5;
    const int g = lane >> 2, q = lane & 3;
    const int e0 = blockIdx.x * 256;
    const int rb = w * 32;

    for (int idx = t; idx < 256 * 32; idx += 256) {
        const int el = idx >> 5, pu = idx & 31;
        const int e = e0 + el;
        Ss[el * 33 + pu] = (e < E) ? g_scal[e * 32 + 2 * (pu & 15) + (pu >> 4)] : 0.f;
    }
    __syncthreads();

    {
        float acc[16][8];
#pragma unroll
        for (int c = 0; c < 16; c++)
#pragma unroll
            for (int j = 0; j < 8; j++) acc[c][j] = 0.f;

#pragma unroll 1
        for (int ks = 0; ks < 20; ks++) {
            const int k0 = ks * 8;
            uint32_t a[2][4];
#pragma unroll
            for (int m = 0; m < 2; m++) {
                const int er0 = e0 + rb + 16 * m + g;
                a[m][0] = fbits(l2w_xval(er0,     k0 + q,     E));
                a[m][1] = fbits(l2w_xval(er0 + 8, k0 + q,     E));
                a[m][2] = fbits(l2w_xval(er0,     k0 + q + 4, E));
                a[m][3] = fbits(l2w_xval(er0 + 8, k0 + q + 4, E));
            }
#pragma unroll
            for (int ch = 0; ch < 16; ch++) {
                const float2 b = *reinterpret_cast<const float2*>(
                    &g_w1f[(ch * 20 + ks) * 64 + lane * 2]);
                mma_tf32(acc[ch][0], acc[ch][1], acc[ch][2], acc[ch][3],
                         a[0][0], a[0][1], a[0][2], a[0][3], fbits(b.x), fbits(b.y));
                mma_tf32(acc[ch][4], acc[ch][5], acc[ch][6], acc[ch][7],
                         a[1][0], a[1][1], a[1][2], a[1][3], fbits(b.x), fbits(b.y));
            }
        }
#pragma unroll
        for (int ch = 0; ch < 16; ch++) {
#pragma unroll
            for (int m = 0; m < 2; m++)
#pragma unroll
                for (int s = 0; s < 2; s++) {
                    const int row = rb + 16 * m + 8 * s + g;
                    const int col = ch * 8 + 2 * q;
                    Hs[row * H_STR + col]     = tf32r(silu_f(acc[ch][4 * m + 2 * s + 0]));
                    Hs[row * H_STR + col + 1] = tf32r(silu_f(acc[ch][4 * m + 2 * s + 1]));
                }
        }
        __syncwarp();
    }

    uint32_t Af[16][2][4];
#pragma unroll
    for (int ks = 0; ks < 16; ks++) {
        const int k0 = ks * 8;
#pragma unroll
        for (int m = 0; m < 2; m++) {
            const int r0 = rb + 16 * m + g;
            Af[ks][m][0] = fbits(Hs[r0 * H_STR + k0 + q]);
            Af[ks][m][1] = fbits(Hs[(r0 + 8) * H_STR + k0 + q]);
            Af[ks][m][2] = fbits(Hs[r0 * H_STR + k0 + q + 4]);
            Af[ks][m][3] = fbits(Hs[(r0 + 8) * H_STR + k0 + q + 4]);
        }
    }

    float fs[4][2][2];
    float fv[4][2][2][3];
#pragma unroll
    for (int rg = 0; rg < 4; rg++)
#pragma unroll
        for (int h = 0; h < 2; h++)
#pragma unroll
            for (int c = 0; c < 2; c++) {
                fs[rg][h][c] = 0.f;
                fv[rg][h][c][0] = 0.f; fv[rg][h][c][1] = 0.f; fv[rg][h][c][2] = 0.f;
            }

#pragma unroll 1
    for (int blk = 0; blk < 10; blk++) {
        if (blk >= 4) {
            __syncthreads();
            const int pb3 = (blk - 4) * 24;
            for (int idx = t; idx < 256 * 24; idx += 256) {
                const int el = idx / 24, c = idx - el * 24;
                const int e = e0 + el;
                Vs[el * 25 + c] = (e < E) ? g_V[e * 144 + pb3 + c] : 0.f;
            }
            __syncthreads();
        }
#pragma unroll 1
        for (int j = 0; j < 8; j++) {
            const int pu = blk * 8 + j;
#pragma unroll
            for (int h = 0; h < 2; h++) {
                float d[8];
#pragma unroll
                for (int x = 0; x < 8; x++) d[x] = 0.f;
                const int fb = ((pu * 2 + h) * 16) * 64;
#pragma unroll
                for (int ks = 0; ks < 16; ks++) {
                    const float2 b = *reinterpret_cast<const float2*>(
                        &g_w2f[fb + ks * 64 + lane * 2]);
                    mma_tf32(d[0], d[1], d[2], d[3],
                             Af[ks][0][0], Af[ks][0][1], Af[ks][0][2], Af[ks][0][3],
                             fbits(b.x), fbits(b.y));
                    mma_tf32(d[4], d[5], d[6], d[7],
                             Af[ks][1][0], Af[ks][1][1], Af[ks][1][2], Af[ks][1][3],
                             fbits(b.x), fbits(b.y));
                }
                if (blk < 4) {
#pragma unroll
                    for (int rg = 0; rg < 4; rg++) {
                        const float s = Ss[(rb + rg * 8 + g) * 33 + pu];
                        fs[rg][h][0] = fmaf(s, d[2 * rg + 0], fs[rg][h][0]);
                        fs[rg][h][1] = fmaf(s, d[2 * rg + 1], fs[rg][h][1]);
                    }
                } else {
#pragma unroll
                    for (int rg = 0; rg < 4; rg++) {
                        const int base = (rb + rg * 8 + g) * 25 + j * 3;
                        const float v0 = Vs[base], v1 = Vs[base + 1], v2 = Vs[base + 2];
#pragma unroll
                        for (int c = 0; c < 2; c++) {
                            const float dd = d[2 * rg + c];
                            fv[rg][h][c][0] = fmaf(dd, v0, fv[rg][h][c][0]);
                            fv[rg][h][c][1] = fmaf(dd, v1, fv[rg][h][c][1]);
                            fv[rg][h][c][2] = fmaf(dd, v2, fv[rg][h][c][2]);
                        }
                    }
                }
            }
        }
    }

#pragma unroll
    for (int rg = 0; rg < 4; rg++) {
        const int e = e0 + rb + rg * 8 + g;
        if (e >= E) continue;
#pragma unroll
        for (int h = 0; h < 2; h++)
#pragma unroll
            for (int c = 0; c < 2; c++) {
                const int v = h * 8 + 2 * q + c;
                g_fs[e * 16 + v] = C_FS * fs[rg][h][c];
                g_fv[e * 48 + v * 3 + 0] = C_FV * fv[rg][h][c][0];
                g_fv[e * 48 + v * 3 + 1] = C_FV * fv[rg][h][c][1];
                g_fv[e * 48 + v * 3 + 2] = C_FV * fv[rg][h][c][2];
            }
    }
}

// ---------------- final output ----------------
__global__ void k_out(float* __restrict__ out, int E) {
    const int idx = blockIdx.x * blockDim.x + threadIdx.x;
    if (idx >= E * 3) return;
    const int e = idx / 3, i = idx - e * 3;
    float acc = 0.f;
#pragma unroll
    for (int u = 0; u < 16; u++)
        acc = fmaf(g_wenv1[e * 16 + u], g_fv[e * 48 + u * 3 + i], acc);
    out[idx] = INV_SM * acc;
}

// ---------------- host driver ----------------
extern "C" void kernel_launch(void* const* d_in, const int* in_sizes, int n_in,
                              void* d_out, int out_size) {
    const float* edge_attr  = (const float*)d_in[0];
    const float* node_attrs = (const float*)d_in[1];
    const float* edge_embed = (const float*)d_in[2];
    const float* edge_u     = (const float*)d_in[3];
    const int*   edge_index = (const int*)d_in[4];
    const float* w2b1    = (const float*)d_in[5];
    const float* w2b2    = (const float*)d_in[6];
    const float* lat1_w1 = (const float*)d_in[7];
    const float* lat1_w2 = (const float*)d_in[8];
    const float* env0_w1 = (const float*)d_in[9];
    const float* env0_w2 = (const float*)d_in[10];
    const float* env1_w1 = (const float*)d_in[11];
    const float* env1_w2 = (const float*)d_in[12];
    const float* l2w0_w1 = (const float*)d_in[13];
    const float* l2w0_w2 = (const float*)d_in[14];
    const float* l2w1_w1 = (const float*)d_in[15];
    const float* l2w1_w2 = (const float*)d_in[16];
    const float* envlin_ws = (const float*)d_in[17];
    const float* envlin_wv = (const float*)d_in[18];
    const float* fl2w_w1 = (const float*)d_in[19];
    const float* fl2w_w2 = (const float*)d_in[20];
    float* out = (float*)d_out;

    const int E = in_sizes[0] / 4;
    const int N = in_sizes[1] / 4;
    if (E > MAX_E || N > MAX_N) return;

    float *p_lat, *p_scal, *p_w0, *p_wenv1, *p_env_s, *p_env_v;
    cudaGetSymbolAddress((void**)&p_lat, g_lat);
    cudaGetSymbolAddress((void**)&p_scal, g_scal);
    cudaGetSymbolAddress((void**)&p_w0, g_w0);
    cudaGetSymbolAddress((void**)&p_wenv1, g_wenv1);
    cudaGetSymbolAddress((void**)&p_env_s, g_env_s);
    cudaGetSymbolAddress((void**)&p_env_v, g_env_v);

    const int smM160 = 128 * 165 * 4;   // 84480
    const int smM128 = 128 * 133 * 4;   // 68096

    cudaFuncSetAttribute((const void*)k_mlp_tc<16, 2,16,2,2>, cudaFuncAttributeMaxDynamicSharedMemorySize, smM128);
    cudaFuncSetAttribute((const void*)k_mlp_tc<128,16, 8,0,0>, cudaFuncAttributeMaxDynamicSharedMemorySize, smM128);
    cudaFuncSetAttribute((const void*)k_mlp_tc<160,20,16,1,1>, cudaFuncAttributeMaxDynamicSharedMemorySize, smM160);
    cudaFuncSetAttribute((const void*)k_mlp_tc<128,16, 4,0,0>, cudaFuncAttributeMaxDynamicSharedMemorySize, smM128);
    cudaFuncSetAttribute((const void*)k_mlp_tc<160,20, 2,1,0>, cudaFuncAttributeMaxDynamicSharedMemorySize, smM160);
    cudaFuncSetAttribute((const void*)k_l2w_ts, cudaFuncAttributeMaxDynamicSharedMemorySize, L2W_SMEM_B);

    const int nbM   = (E + 127) / 128;
    const int nb256 = (E + 255) / 256;
    const int nb16  = (E * 16 + 255) / 256;

    auto packN = [](int KS1, int NCH2) { return ((16 * KS1 + NCH2 * 16) * 32 + 255) / 256; };

    // ---- stage 0: first MLP (gather, cut-scale epi) + env0 ----
    k_pack_mlp<<<packN(2, 16), 256>>>(w2b1, 2, w2b2, 16, 128);
    k_mlp_tc<16, 2,16,2,2><<<nbM, 256, smM128>>>(node_attrs, edge_embed, edge_u, edge_index, p_lat, E);
    k_pack_mlp<<<packN(16, 8), 256>>>(env0_w1, 16, env0_w2, 8, 64);
    k_mlp_tc<128,16, 8,0,0><<<nbM, 256, smM128>>>(p_lat, p_lat, edge_u, edge_index, p_w0, E);
    k_weighter<<<nb16, 256>>>(edge_attr, E);

    // ---- layer 0 ----
    cudaMemsetAsync(p_env_s, 0, (size_t)N * 16 * sizeof(float));
    cudaMemsetAsync(p_env_v, 0, (size_t)N * 48 * sizeof(float));
    k_scatter<<<nb16, 256>>>(p_w0, 64, 32, edge_attr, edge_index, E);
    k_envlin<<<(N * 16 + 255) / 256, 256>>>(envlin_ws, envlin_wv, N);
    k_combine<<<nb16, 256>>>(edge_index, E);
    k_pack_w1<<<(16 * 20 * 64 + 255) / 256, 256>>>(l2w0_w1);
    k_pack_w2<<<(80 * 2 * 16 * 64 + 255) / 256, 256>>>(l2w0_w2);
    k_l2w_ts<<<nb256, 256, L2W_SMEM_B>>>(E);

    // ---- layer 1 ----
    k_pack_mlp<<<packN(20, 16), 256>>>(lat1_w1, 20, lat1_w2, 16, 128);
    k_mlp_tc<160,20,16,1,1><<<nbM, 256, smM160>>>(p_lat, p_scal, edge_u, edge_index, p_lat, E);
    k_pack_mlp<<<packN(16, 4), 256>>>(env1_w1, 16, env1_w2, 4, 32);
    k_mlp_tc<128,16, 4,0,0><<<nbM, 256, smM128>>>(p_lat, p_lat, edge_u, edge_index, p_wenv1, E);
    cudaMemsetAsync(p_env_s, 0, (size_t)N * 16 * sizeof(float));
    cudaMemsetAsync(p_env_v, 0, (size_t)N * 48 * sizeof(float));
    k_scatter<<<nb16, 256>>>(p_wenv1, 32, 0, edge_attr, edge_index, E);
    k_envlin<<<(N * 16 + 255) / 256, 256>>>(envlin_ws + 256, envlin_wv + 256, N);
    k_combine<<<nb16, 256>>>(edge_index, E);
    k_pack_w1<<<(16 * 20 * 64 + 255) / 256, 256>>>(l2w1_w1);
    k_pack_w2<<<(80 * 2 * 16 * 64 + 255) / 256, 256>>>(l2w1_w2);
    k_l2w_ts<<<nb256, 256, L2W_SMEM_B>>>(E);

    // ---- final: fw MLP + contraction ----
    k_pack_mlp<<<packN(20, 2), 256>>>(fl2w_w1, 20, fl2w_w2, 2, 16);
    k_mlp_tc<160,20, 2,1,0><<<nbM, 256, smM160>>>(p_lat, p_scal, edge_u, edge_index, p_wenv1, E);
    k_out<<<(E * 3 + 255) / 256, 256>>>(out, E);
}